// round 2
// baseline (speedup 1.0000x reference)
#include <cuda_runtime.h>
#include <stdint.h>

#define NN   50000
#define FIN  512
#define FH   128
#define FO   40
#define FC   256

// ---------------- scratch (device globals; no allocation allowed) ----------
__device__ float g_deg[NN];
__device__ float g_dis[NN];
__device__ float g_hW1[NN * FH];
__device__ float g_agg1[NN * FH];
__device__ float g_h1[NN * FH];
__device__ float g_hW2[NN * FH];
__device__ float g_agg2[NN * FH];
__device__ float g_h2[NN * FH];
__device__ float g_hW3[NN * FO];
__device__ float g_agg3[NN * FO];
__device__ float g_h3[NN * FO];
__device__ float g_hp[NN * FO];
__device__ float g_c1[NN * FC];
__device__ float g_c2[NN * FC];
__device__ float g_c3[NN * FO];

// ---------------- threefry2x32 (JAX-compatible) ----------------------------
__host__ __device__ __forceinline__ void threefry2x32(uint32_t k0, uint32_t k1,
                                                      uint32_t& x0, uint32_t& x1) {
    uint32_t ks0 = k0, ks1 = k1, ks2 = k0 ^ k1 ^ 0x1BD11BDAu;
    x0 += ks0; x1 += ks1;
#define TF_RND(r) { x0 += x1; x1 = (x1 << (r)) | (x1 >> (32 - (r))); x1 ^= x0; }
    TF_RND(13) TF_RND(15) TF_RND(26) TF_RND(6)   x0 += ks1; x1 += ks2 + 1u;
    TF_RND(17) TF_RND(29) TF_RND(16) TF_RND(24)  x0 += ks2; x1 += ks0 + 2u;
    TF_RND(13) TF_RND(15) TF_RND(26) TF_RND(6)   x0 += ks0; x1 += ks1 + 3u;
    TF_RND(17) TF_RND(29) TF_RND(16) TF_RND(24)  x0 += ks1; x1 += ks2 + 4u;
    TF_RND(13) TF_RND(15) TF_RND(26) TF_RND(6)   x0 += ks2; x1 += ks0 + 5u;
#undef TF_RND
}

// keep-mask for dropout(p=0.5), JAX partitionable threefry:
// bits(i) = o0 ^ o1 of threefry2x32(key, (hi32(i)=0, lo32(i)=i)); keep iff bit31==0.
__device__ __forceinline__ bool tf_keep(uint32_t k0, uint32_t k1, uint32_t idx) {
    uint32_t x0 = 0u, x1 = idx;
    threefry2x32(k0, k1, x0, x1);
    return (((x0 ^ x1) >> 31) == 0u);
}

// ---------------- degree / normalization -----------------------------------
__global__ void k_deg(const int* __restrict__ dst, int E) {
    int i = blockIdx.x * blockDim.x + threadIdx.x;
    if (i < E) atomicAdd(&g_deg[dst[i]], 1.0f);
}

__global__ void k_dis() {
    int i = blockIdx.x * blockDim.x + threadIdx.x;
    if (i < NN) g_dis[i] = rsqrtf(1.0f + g_deg[i]);
}

// ---------------- SGEMM: C[M,N] = A[M,K] @ W[K,N] (+bias)(+relu) -----------
template <bool BIAS, bool RELU>
__global__ void sgemm64(const float* __restrict__ A, const float* __restrict__ W,
                        const float* __restrict__ bias, float* __restrict__ C,
                        int M, int K, int N) {
    const int BM = 64, BN = 64, BK = 16;
    __shared__ float As[BK][BM + 4];   // transposed A tile
    __shared__ float Ws[BK][BN];

    int tid = threadIdx.x;             // 256 threads
    int bm = blockIdx.x * BM, bn = blockIdx.y * BN;
    int tx = tid & 15, ty = tid >> 4;

    int arow  = tid >> 2;              // 0..63
    int acol4 = tid & 3;
    int wrow  = tid >> 4;              // 0..15
    int wcol4 = tid & 15;

    float acc[4][4];
#pragma unroll
    for (int i = 0; i < 4; i++)
#pragma unroll
        for (int j = 0; j < 4; j++) acc[i][j] = 0.0f;

    for (int k0 = 0; k0 < K; k0 += BK) {
        float4 av = make_float4(0.f, 0.f, 0.f, 0.f);
        int gr = bm + arow;
        if (gr < M)
            av = *reinterpret_cast<const float4*>(&A[(size_t)gr * K + k0 + acol4 * 4]);
        As[acol4 * 4 + 0][arow] = av.x;
        As[acol4 * 4 + 1][arow] = av.y;
        As[acol4 * 4 + 2][arow] = av.z;
        As[acol4 * 4 + 3][arow] = av.w;

        float4 wv = make_float4(0.f, 0.f, 0.f, 0.f);
        int gc = bn + wcol4 * 4;
        if (gc < N)
            wv = *reinterpret_cast<const float4*>(&W[(size_t)(k0 + wrow) * N + gc]);
        Ws[wrow][wcol4 * 4 + 0] = wv.x;
        Ws[wrow][wcol4 * 4 + 1] = wv.y;
        Ws[wrow][wcol4 * 4 + 2] = wv.z;
        Ws[wrow][wcol4 * 4 + 3] = wv.w;

        __syncthreads();
#pragma unroll
        for (int k = 0; k < BK; k++) {
            float a[4], w[4];
#pragma unroll
            for (int i = 0; i < 4; i++) a[i] = As[k][ty * 4 + i];
#pragma unroll
            for (int j = 0; j < 4; j++) w[j] = Ws[k][tx * 4 + j];
#pragma unroll
            for (int i = 0; i < 4; i++)
#pragma unroll
                for (int j = 0; j < 4; j++) acc[i][j] = fmaf(a[i], w[j], acc[i][j]);
        }
        __syncthreads();
    }

#pragma unroll
    for (int i = 0; i < 4; i++) {
        int r = bm + ty * 4 + i;
        if (r >= M) continue;
#pragma unroll
        for (int j = 0; j < 4; j++) {
            int c = bn + tx * 4 + j;
            if (c >= N) continue;
            float v = acc[i][j];
            if (BIAS) v += bias[c];
            if (RELU) v = fmaxf(v, 0.0f);
            C[(size_t)r * N + c] = v;
        }
    }
}

// ---------------- edge aggregation (F = 128): 1 float4 per thread ----------
__global__ void k_agg128(const float* __restrict__ hW, const int* __restrict__ src,
                         const int* __restrict__ dst, int E, float* __restrict__ agg) {
    long long t = (long long)blockIdx.x * blockDim.x + threadIdx.x;
    long long total = (long long)E * 32;      // F/4 = 32 float4 lanes per edge
    if (t >= total) return;
    int e = (int)(t >> 5);
    int q = (int)(t & 31);
    int s = __ldg(&src[e]), d = __ldg(&dst[e]);
    float coef = g_dis[s] * g_dis[d];
    float4 v = __ldg(reinterpret_cast<const float4*>(hW) + (size_t)s * 32 + q);
    float* p = agg + ((size_t)d * 32 + q) * 4;
    atomicAdd(p + 0, v.x * coef);
    atomicAdd(p + 1, v.y * coef);
    atomicAdd(p + 2, v.z * coef);
    atomicAdd(p + 3, v.w * coef);
}

// ---------------- edge aggregation (F = 40): 10 float4 lanes per edge ------
__global__ void k_agg40(const float* __restrict__ hW, const int* __restrict__ src,
                        const int* __restrict__ dst, int E, float* __restrict__ agg) {
    long long t = (long long)blockIdx.x * blockDim.x + threadIdx.x;
    long long total = (long long)E * 10;
    if (t >= total) return;
    int e = (int)(t / 10);
    int q = (int)(t - (long long)e * 10);
    int s = __ldg(&src[e]), d = __ldg(&dst[e]);
    float coef = g_dis[s] * g_dis[d];
    float4 v = __ldg(reinterpret_cast<const float4*>(hW) + (size_t)s * 10 + q);
    float* p = agg + ((size_t)d * 10 + q) * 4;
    atomicAdd(p + 0, v.x * coef);
    atomicAdd(p + 1, v.y * coef);
    atomicAdd(p + 2, v.z * coef);
    atomicAdd(p + 3, v.w * coef);
}

// ---------------- finish hidden layer: self-loop + bias + relu + dropout ---
__global__ void k_finish_hid(const float* __restrict__ agg, const float* __restrict__ hW,
                             const float* __restrict__ b, float* __restrict__ out,
                             uint32_t k0, uint32_t k1) {
    int e = blockIdx.x * blockDim.x + threadIdx.x;
    if (e >= NN * FH) return;
    int r = e >> 7, c = e & (FH - 1);
    float di = g_dis[r];
    float v = agg[e] + hW[e] * di * di + b[c];
    v = fmaxf(v, 0.0f);
    out[e] = tf_keep(k0, k1, (uint32_t)e) ? 2.0f * v : 0.0f;
}

// ---------------- finish output GCN layer (F = 40, no relu/dropout) --------
__global__ void k_finish40(const float* __restrict__ agg, const float* __restrict__ hW,
                           const float* __restrict__ b) {
    int e = blockIdx.x * blockDim.x + threadIdx.x;
    if (e >= NN * FO) return;
    int r = e / FO, c = e - r * FO;
    float di = g_dis[r];
    g_h3[e] = agg[e] + hW[e] * di * di + b[c];
}

// ---------------- standalone dropout (comp path, in place) -----------------
__global__ void k_dropout(float* __restrict__ buf, int S, uint32_t k0, uint32_t k1) {
    int e = blockIdx.x * blockDim.x + threadIdx.x;
    if (e >= S) return;
    float a = buf[e];
    buf[e] = tf_keep(k0, k1, (uint32_t)e) ? 2.0f * a : 0.0f;
}

// ---------------- SpMM: hp[r] += val * h3[c] --------------------------------
__global__ void k_spmm(const int* __restrict__ rows, const int* __restrict__ cols,
                       const float* __restrict__ vals, int P) {
    long long t = (long long)blockIdx.x * blockDim.x + threadIdx.x;
    long long total = (long long)P * 10;
    if (t >= total) return;
    int e = (int)(t / 10);
    int q = (int)(t - (long long)e * 10);
    int r = __ldg(&rows[e]), c = __ldg(&cols[e]);
    float val = __ldg(&vals[e]);
    float4 v = __ldg(reinterpret_cast<const float4*>(g_h3) + (size_t)c * 10 + q);
    float* p = g_hp + ((size_t)r * 10 + q) * 4;
    atomicAdd(p + 0, v.x * val);
    atomicAdd(p + 1, v.y * val);
    atomicAdd(p + 2, v.z * val);
    atomicAdd(p + 3, v.w * val);
}

// ---------------- final: z = hp*(1+c3); out = log_softmax(z) ----------------
__global__ void k_final(float* __restrict__ out) {
    int gt = blockIdx.x * blockDim.x + threadIdx.x;
    int w = gt >> 5;
    int lane = gt & 31;
    if (w >= NN) return;

    const float NEG_INF = __int_as_float(0xff800000);
    int c0 = lane;           // always < 40
    int c1 = lane + 32;      // valid iff lane < 8
    size_t base = (size_t)w * FO;

    float z0 = g_hp[base + c0] * (1.0f + g_c3[base + c0]);
    float z1 = (c1 < FO) ? g_hp[base + c1] * (1.0f + g_c3[base + c1]) : NEG_INF;

    float m = fmaxf(z0, z1);
#pragma unroll
    for (int off = 16; off > 0; off >>= 1)
        m = fmaxf(m, __shfl_xor_sync(0xffffffffu, m, off));

    float s = expf(z0 - m) + ((c1 < FO) ? expf(z1 - m) : 0.0f);
#pragma unroll
    for (int off = 16; off > 0; off >>= 1)
        s += __shfl_xor_sync(0xffffffffu, s, off);

    float lse = logf(s) + m;
    out[base + c0] = z0 - lse;
    if (c1 < FO) out[base + c1] = z1 - lse;
}

// ---------------- host launcher ---------------------------------------------
static inline int cdiv(long long a, int b) { return (int)((a + b - 1) / b); }

extern "C" void kernel_launch(void* const* d_in, const int* in_sizes, int n_in,
                              void* d_out, int out_size) {
    const float* x     = (const float*)d_in[0];
    const float* omega = (const float*)d_in[1];
    const int*   ei    = (const int*)d_in[2];
    const int*   prow  = (const int*)d_in[3];
    const int*   pcol  = (const int*)d_in[4];
    const float* pval  = (const float*)d_in[5];
    const float* Wg1 = (const float*)d_in[6];  const float* bg1 = (const float*)d_in[7];
    const float* Wg2 = (const float*)d_in[8];  const float* bg2 = (const float*)d_in[9];
    const float* Wg3 = (const float*)d_in[10]; const float* bg3 = (const float*)d_in[11];
    const float* Wc1 = (const float*)d_in[12]; const float* bc1 = (const float*)d_in[13];
    const float* Wc2 = (const float*)d_in[14]; const float* bc2 = (const float*)d_in[15];
    const float* Wc3 = (const float*)d_in[16]; const float* bc3 = (const float*)d_in[17];

    int E = in_sizes[2] / 2;
    int P = in_sizes[3];
    const int* src = ei;
    const int* dst = ei + E;

    // dropout keys: dk = split(key(7), 4), JAX partitionable ("fold-like"):
    // key_j = threefry2x32(key, x0=hi32(j)=0, x1=lo32(j)=j) -> (out0, out1)
    uint32_t dk[4][2];
    for (int j = 0; j < 4; j++) {
        uint32_t a = 0u, b = (uint32_t)j;
        threefry2x32(0u, 7u, a, b);
        dk[j][0] = a; dk[j][1] = b;
    }

    // symbol addresses
    void *p_deg, *p_hW1, *p_agg1, *p_h1, *p_hW2, *p_agg2, *p_h2;
    void *p_hW3, *p_agg3, *p_hp, *p_c1, *p_c2, *p_c3;
    cudaGetSymbolAddress(&p_deg, g_deg);
    cudaGetSymbolAddress(&p_hW1, g_hW1);   cudaGetSymbolAddress(&p_agg1, g_agg1);
    cudaGetSymbolAddress(&p_h1, g_h1);     cudaGetSymbolAddress(&p_hW2, g_hW2);
    cudaGetSymbolAddress(&p_agg2, g_agg2); cudaGetSymbolAddress(&p_h2, g_h2);
    cudaGetSymbolAddress(&p_hW3, g_hW3);   cudaGetSymbolAddress(&p_agg3, g_agg3);
    cudaGetSymbolAddress(&p_hp, g_hp);
    cudaGetSymbolAddress(&p_c1, g_c1);     cudaGetSymbolAddress(&p_c2, g_c2);
    cudaGetSymbolAddress(&p_c3, g_c3);

    cudaStream_t st = 0;
    cudaMemsetAsync(p_deg,  0, NN * sizeof(float), st);
    cudaMemsetAsync(p_agg1, 0, (size_t)NN * FH * sizeof(float), st);
    cudaMemsetAsync(p_agg2, 0, (size_t)NN * FH * sizeof(float), st);
    cudaMemsetAsync(p_agg3, 0, (size_t)NN * FO * sizeof(float), st);
    cudaMemsetAsync(p_hp,   0, (size_t)NN * FO * sizeof(float), st);

    // degree / normalization
    k_deg<<<cdiv(E, 256), 256, 0, st>>>(dst, E);
    k_dis<<<cdiv(NN, 256), 256, 0, st>>>();

    dim3 blk(256);

    // ---- GCN layer 1: x @ W_g1 -> aggregate -> finish(+dropout dk0) ----
    sgemm64<false, false><<<dim3(cdiv(NN, 64), cdiv(FH, 64)), blk, 0, st>>>(
        x, Wg1, nullptr, (float*)p_hW1, NN, FIN, FH);
    k_agg128<<<cdiv((long long)E * 32, 256), blk, 0, st>>>(
        (const float*)p_hW1, src, dst, E, (float*)p_agg1);
    k_finish_hid<<<cdiv(NN * FH, 256), blk, 0, st>>>(
        (const float*)p_agg1, (const float*)p_hW1, bg1, (float*)p_h1, dk[0][0], dk[0][1]);

    // ---- GCN layer 2 ----
    sgemm64<false, false><<<dim3(cdiv(NN, 64), cdiv(FH, 64)), blk, 0, st>>>(
        (const float*)p_h1, Wg2, nullptr, (float*)p_hW2, NN, FH, FH);
    k_agg128<<<cdiv((long long)E * 32, 256), blk, 0, st>>>(
        (const float*)p_hW2, src, dst, E, (float*)p_agg2);
    k_finish_hid<<<cdiv(NN * FH, 256), blk, 0, st>>>(
        (const float*)p_agg2, (const float*)p_hW2, bg2, (float*)p_h2, dk[1][0], dk[1][1]);

    // ---- GCN layer 3 (no relu/dropout) ----
    sgemm64<false, false><<<dim3(cdiv(NN, 64), 1), blk, 0, st>>>(
        (const float*)p_h2, Wg3, nullptr, (float*)p_hW3, NN, FH, FO);
    k_agg40<<<cdiv((long long)E * 10, 256), blk, 0, st>>>(
        (const float*)p_hW3, src, dst, E, (float*)p_agg3);
    k_finish40<<<cdiv(NN * FO, 256), blk, 0, st>>>(
        (const float*)p_agg3, (const float*)p_hW3, bg3);

    // ---- SpMM with partition matrix ----
    k_spmm<<<cdiv((long long)P * 10, 256), blk, 0, st>>>(prow, pcol, pval, P);

    // ---- compensation MLP ----
    sgemm64<true, true><<<dim3(cdiv(NN, 64), cdiv(FC, 64)), blk, 0, st>>>(
        omega, Wc1, bc1, (float*)p_c1, NN, FIN, FC);
    k_dropout<<<cdiv(NN * FC, 256), blk, 0, st>>>((float*)p_c1, NN * FC, dk[2][0], dk[2][1]);

    sgemm64<true, true><<<dim3(cdiv(NN, 64), cdiv(FC, 64)), blk, 0, st>>>(
        (const float*)p_c1, Wc2, bc2, (float*)p_c2, NN, FC, FC);
    k_dropout<<<cdiv(NN * FC, 256), blk, 0, st>>>((float*)p_c2, NN * FC, dk[3][0], dk[3][1]);

    sgemm64<true, false><<<dim3(cdiv(NN, 64), 1), blk, 0, st>>>(
        (const float*)p_c2, Wc3, bc3, (float*)p_c3, NN, FC, FO);

    // ---- combine + log_softmax ----
    k_final<<<cdiv((long long)NN * 32, 256), blk, 0, st>>>((float*)d_out);
}

// round 3
// speedup vs baseline: 1.2031x; 1.2031x over previous
#include <cuda_runtime.h>
#include <stdint.h>

#define NN   50000
#define FIN  512
#define FH   128
#define FO   40
#define FC   256

// ---------------- scratch (device globals; no allocation allowed) ----------
__device__ float g_deg[NN];
__device__ float g_dis[NN];
__device__ float g_hs1[NN * FH];    // dis[r] * (x @ Wg1)
__device__ float g_agg1[NN * FH];
__device__ float g_h1[NN * FH];
__device__ float g_hs2[NN * FH];
__device__ float g_agg2[NN * FH];
__device__ float g_h2[NN * FH];
__device__ float g_hs3[NN * FO];
__device__ float g_agg3[NN * FO];
__device__ float g_h3[NN * FO];
__device__ float g_hp[NN * FO];
__device__ float g_c1[NN * FC];
__device__ float g_c2[NN * FC];
__device__ float g_c3[NN * FO];

// ---------------- threefry2x32 (JAX-compatible, partitionable) -------------
__host__ __device__ __forceinline__ void threefry2x32(uint32_t k0, uint32_t k1,
                                                      uint32_t& x0, uint32_t& x1) {
    uint32_t ks0 = k0, ks1 = k1, ks2 = k0 ^ k1 ^ 0x1BD11BDAu;
    x0 += ks0; x1 += ks1;
#define TF_RND(r) { x0 += x1; x1 = (x1 << (r)) | (x1 >> (32 - (r))); x1 ^= x0; }
    TF_RND(13) TF_RND(15) TF_RND(26) TF_RND(6)   x0 += ks1; x1 += ks2 + 1u;
    TF_RND(17) TF_RND(29) TF_RND(16) TF_RND(24)  x0 += ks2; x1 += ks0 + 2u;
    TF_RND(13) TF_RND(15) TF_RND(26) TF_RND(6)   x0 += ks0; x1 += ks1 + 3u;
    TF_RND(17) TF_RND(29) TF_RND(16) TF_RND(24)  x0 += ks1; x1 += ks2 + 4u;
    TF_RND(13) TF_RND(15) TF_RND(26) TF_RND(6)   x0 += ks2; x1 += ks0 + 5u;
#undef TF_RND
}

// keep iff bit31 of (o0^o1) of threefry(key, (0, idx)) is 0  (p=0.5 dropout)
__device__ __forceinline__ bool tf_keep(uint32_t k0, uint32_t k1, uint32_t idx) {
    uint32_t x0 = 0u, x1 = idx;
    threefry2x32(k0, k1, x0, x1);
    return (((x0 ^ x1) >> 31) == 0u);
}

// ---------------- vector reduction (sm_90+: red.global.add.v4.f32) ---------
__device__ __forceinline__ void red_add_v4(float* p, float4 v) {
    asm volatile("red.global.add.v4.f32 [%0], {%1, %2, %3, %4};"
                 :: "l"(p), "f"(v.x), "f"(v.y), "f"(v.z), "f"(v.w)
                 : "memory");
}

// ---------------- degree / normalization -----------------------------------
__global__ void k_deg(const int* __restrict__ dst, int E) {
    int i = blockIdx.x * blockDim.x + threadIdx.x;
    if (i < E) atomicAdd(&g_deg[dst[i]], 1.0f);
}

__global__ void k_dis() {
    int i = blockIdx.x * blockDim.x + threadIdx.x;
    if (i < NN) g_dis[i] = rsqrtf(1.0f + g_deg[i]);
}

// ---------------- SGEMM 128x128x8, 256 thr, 8x8/thread ---------------------
// C[M,N] = A[M,K] @ W[K,N]; optional bias/relu; optional row scale by g_dis.
// Requires: K % 8 == 0, N % 128 == 0 (true for N=128,256 layers).
template <bool BIAS, bool RELU, bool SCALE>
__global__ void __launch_bounds__(256, 2)
sgemm128(const float* __restrict__ A, const float* __restrict__ W,
         const float* __restrict__ bias, float* __restrict__ C,
         int M, int K, int N) {
    __shared__ float As[8][132];
    __shared__ float Ws[8][128];

    int tid = threadIdx.x;
    int bm = blockIdx.x * 128, bn = blockIdx.y * 128;

    int arow = tid >> 1, akq = tid & 1;      // A-tile loader: row 0..127, half-k
    int wk   = tid >> 5, wn4 = tid & 31;     // W-tile loader: k 0..7, float4 col

    int tx = tid & 15, ty = tid >> 4;        // compute grid 16x16

    float acc[8][8];
#pragma unroll
    for (int i = 0; i < 8; i++)
#pragma unroll
        for (int j = 0; j < 8; j++) acc[i][j] = 0.0f;

    for (int k0 = 0; k0 < K; k0 += 8) {
        float4 av = make_float4(0.f, 0.f, 0.f, 0.f);
        int gr = bm + arow;
        if (gr < M)
            av = *reinterpret_cast<const float4*>(&A[(size_t)gr * K + k0 + akq * 4]);
        As[akq * 4 + 0][arow] = av.x;
        As[akq * 4 + 1][arow] = av.y;
        As[akq * 4 + 2][arow] = av.z;
        As[akq * 4 + 3][arow] = av.w;

        float4 wv = *reinterpret_cast<const float4*>(&W[(size_t)(k0 + wk) * N + bn + wn4 * 4]);
        *reinterpret_cast<float4*>(&Ws[wk][wn4 * 4]) = wv;

        __syncthreads();
#pragma unroll
        for (int k = 0; k < 8; k++) {
            float a[8], w[8];
            *reinterpret_cast<float4*>(&a[0]) = *reinterpret_cast<const float4*>(&As[k][ty * 8]);
            *reinterpret_cast<float4*>(&a[4]) = *reinterpret_cast<const float4*>(&As[k][ty * 8 + 4]);
            *reinterpret_cast<float4*>(&w[0]) = *reinterpret_cast<const float4*>(&Ws[k][tx * 8]);
            *reinterpret_cast<float4*>(&w[4]) = *reinterpret_cast<const float4*>(&Ws[k][tx * 8 + 4]);
#pragma unroll
            for (int i = 0; i < 8; i++)
#pragma unroll
                for (int j = 0; j < 8; j++) acc[i][j] = fmaf(a[i], w[j], acc[i][j]);
        }
        __syncthreads();
    }

#pragma unroll
    for (int i = 0; i < 8; i++) {
        int r = bm + ty * 8 + i;
        if (r >= M) continue;
        float sc = SCALE ? g_dis[r] : 1.0f;
        float out[8];
#pragma unroll
        for (int j = 0; j < 8; j++) {
            float v = acc[i][j];
            if (BIAS) v += bias[bn + tx * 8 + j];
            if (RELU) v = fmaxf(v, 0.0f);
            if (SCALE) v *= sc;
            out[j] = v;
        }
        *reinterpret_cast<float4*>(&C[(size_t)r * N + bn + tx * 8])     = *reinterpret_cast<float4*>(&out[0]);
        *reinterpret_cast<float4*>(&C[(size_t)r * N + bn + tx * 8 + 4]) = *reinterpret_cast<float4*>(&out[4]);
    }
}

// ---------------- SGEMM 64x64x16 (for N=40 layers) -------------------------
template <bool BIAS, bool RELU, bool SCALE>
__global__ void sgemm64(const float* __restrict__ A, const float* __restrict__ W,
                        const float* __restrict__ bias, float* __restrict__ C,
                        int M, int K, int N) {
    const int BM = 64, BN = 64, BK = 16;
    __shared__ float As[BK][BM + 4];
    __shared__ float Ws[BK][BN];

    int tid = threadIdx.x;
    int bm = blockIdx.x * BM, bn = blockIdx.y * BN;
    int tx = tid & 15, ty = tid >> 4;

    int arow  = tid >> 2, acol4 = tid & 3;
    int wrow  = tid >> 4, wcol4 = tid & 15;

    float acc[4][4];
#pragma unroll
    for (int i = 0; i < 4; i++)
#pragma unroll
        for (int j = 0; j < 4; j++) acc[i][j] = 0.0f;

    for (int k0 = 0; k0 < K; k0 += BK) {
        float4 av = make_float4(0.f, 0.f, 0.f, 0.f);
        int gr = bm + arow;
        if (gr < M)
            av = *reinterpret_cast<const float4*>(&A[(size_t)gr * K + k0 + acol4 * 4]);
        As[acol4 * 4 + 0][arow] = av.x;
        As[acol4 * 4 + 1][arow] = av.y;
        As[acol4 * 4 + 2][arow] = av.z;
        As[acol4 * 4 + 3][arow] = av.w;

        float4 wv = make_float4(0.f, 0.f, 0.f, 0.f);
        int gc = bn + wcol4 * 4;
        if (gc < N)
            wv = *reinterpret_cast<const float4*>(&W[(size_t)(k0 + wrow) * N + gc]);
        Ws[wrow][wcol4 * 4 + 0] = wv.x;
        Ws[wrow][wcol4 * 4 + 1] = wv.y;
        Ws[wrow][wcol4 * 4 + 2] = wv.z;
        Ws[wrow][wcol4 * 4 + 3] = wv.w;

        __syncthreads();
#pragma unroll
        for (int k = 0; k < BK; k++) {
            float a[4], w[4];
#pragma unroll
            for (int i = 0; i < 4; i++) a[i] = As[k][ty * 4 + i];
#pragma unroll
            for (int j = 0; j < 4; j++) w[j] = Ws[k][tx * 4 + j];
#pragma unroll
            for (int i = 0; i < 4; i++)
#pragma unroll
                for (int j = 0; j < 4; j++) acc[i][j] = fmaf(a[i], w[j], acc[i][j]);
        }
        __syncthreads();
    }

#pragma unroll
    for (int i = 0; i < 4; i++) {
        int r = bm + ty * 4 + i;
        if (r >= M) continue;
        float sc = SCALE ? g_dis[r] : 1.0f;
#pragma unroll
        for (int j = 0; j < 4; j++) {
            int c = bn + tx * 4 + j;
            if (c >= N) continue;
            float v = acc[i][j];
            if (BIAS) v += bias[c];
            if (RELU) v = fmaxf(v, 0.0f);
            if (SCALE) v *= sc;
            C[(size_t)r * N + c] = v;
        }
    }
}

// ---------------- edge aggregation (F = 128): pure sum of hs ---------------
__global__ void k_agg128(const float* __restrict__ hs, const int* __restrict__ src,
                         const int* __restrict__ dst, int E, float* __restrict__ agg) {
    long long t = (long long)blockIdx.x * blockDim.x + threadIdx.x;
    long long total = (long long)E * 32;
    if (t >= total) return;
    int e = (int)(t >> 5);
    int q = (int)(t & 31);
    int s = __ldg(&src[e]), d = __ldg(&dst[e]);
    float4 v = __ldg(reinterpret_cast<const float4*>(hs) + (size_t)s * 32 + q);
    red_add_v4(agg + ((size_t)d * 32 + q) * 4, v);
}

// ---------------- edge aggregation (F = 40) --------------------------------
__global__ void k_agg40(const float* __restrict__ hs, const int* __restrict__ src,
                        const int* __restrict__ dst, int E, float* __restrict__ agg) {
    long long t = (long long)blockIdx.x * blockDim.x + threadIdx.x;
    long long total = (long long)E * 10;
    if (t >= total) return;
    int e = (int)(t / 10);
    int q = (int)(t - (long long)e * 10);
    int s = __ldg(&src[e]), d = __ldg(&dst[e]);
    float4 v = __ldg(reinterpret_cast<const float4*>(hs) + (size_t)s * 10 + q);
    red_add_v4(agg + ((size_t)d * 10 + q) * 4, v);
}

// ---------------- finish hidden: v = dis*(agg+hs)+b, relu, dropout ---------
__global__ void k_finish_hid(const float* __restrict__ agg, const float* __restrict__ hs,
                             const float* __restrict__ b, float* __restrict__ out,
                             uint32_t k0, uint32_t k1) {
    int e = blockIdx.x * blockDim.x + threadIdx.x;
    if (e >= NN * FH) return;
    int r = e >> 7, c = e & (FH - 1);
    float v = g_dis[r] * (agg[e] + hs[e]) + b[c];
    v = fmaxf(v, 0.0f);
    out[e] = tf_keep(k0, k1, (uint32_t)e) ? 2.0f * v : 0.0f;
}

// ---------------- finish output GCN layer (F = 40) -------------------------
__global__ void k_finish40(const float* __restrict__ agg, const float* __restrict__ hs,
                           const float* __restrict__ b) {
    int e = blockIdx.x * blockDim.x + threadIdx.x;
    if (e >= NN * FO) return;
    int r = e / FO, c = e - r * FO;
    g_h3[e] = g_dis[r] * (agg[e] + hs[e]) + b[c];
}

// ---------------- standalone dropout (comp path, in place) -----------------
__global__ void k_dropout(float* __restrict__ buf, int S, uint32_t k0, uint32_t k1) {
    int e = blockIdx.x * blockDim.x + threadIdx.x;
    if (e >= S) return;
    float a = buf[e];
    buf[e] = tf_keep(k0, k1, (uint32_t)e) ? 2.0f * a : 0.0f;
}

// ---------------- SpMM: hp[r] += val * h3[c] --------------------------------
__global__ void k_spmm(const int* __restrict__ rows, const int* __restrict__ cols,
                       const float* __restrict__ vals, int P) {
    long long t = (long long)blockIdx.x * blockDim.x + threadIdx.x;
    long long total = (long long)P * 10;
    if (t >= total) return;
    int e = (int)(t / 10);
    int q = (int)(t - (long long)e * 10);
    int r = __ldg(&rows[e]), c = __ldg(&cols[e]);
    float val = __ldg(&vals[e]);
    float4 v = __ldg(reinterpret_cast<const float4*>(g_h3) + (size_t)c * 10 + q);
    v.x *= val; v.y *= val; v.z *= val; v.w *= val;
    red_add_v4(g_hp + ((size_t)r * 10 + q) * 4, v);
}

// ---------------- final: z = hp*(1+c3); out = log_softmax(z) ----------------
__global__ void k_final(float* __restrict__ out) {
    int gt = blockIdx.x * blockDim.x + threadIdx.x;
    int w = gt >> 5;
    int lane = gt & 31;
    if (w >= NN) return;

    const float NEG_INF = __int_as_float(0xff800000);
    int c0 = lane;
    int c1 = lane + 32;
    size_t base = (size_t)w * FO;

    float z0 = g_hp[base + c0] * (1.0f + g_c3[base + c0]);
    float z1 = (c1 < FO) ? g_hp[base + c1] * (1.0f + g_c3[base + c1]) : NEG_INF;

    float m = fmaxf(z0, z1);
#pragma unroll
    for (int off = 16; off > 0; off >>= 1)
        m = fmaxf(m, __shfl_xor_sync(0xffffffffu, m, off));

    float s = expf(z0 - m) + ((c1 < FO) ? expf(z1 - m) : 0.0f);
#pragma unroll
    for (int off = 16; off > 0; off >>= 1)
        s += __shfl_xor_sync(0xffffffffu, s, off);

    float lse = logf(s) + m;
    out[base + c0] = z0 - lse;
    if (c1 < FO) out[base + c1] = z1 - lse;
}

// ---------------- host launcher ---------------------------------------------
static inline int cdiv(long long a, int b) { return (int)((a + b - 1) / b); }

extern "C" void kernel_launch(void* const* d_in, const int* in_sizes, int n_in,
                              void* d_out, int out_size) {
    const float* x     = (const float*)d_in[0];
    const float* omega = (const float*)d_in[1];
    const int*   ei    = (const int*)d_in[2];
    const int*   prow  = (const int*)d_in[3];
    const int*   pcol  = (const int*)d_in[4];
    const float* pval  = (const float*)d_in[5];
    const float* Wg1 = (const float*)d_in[6];  const float* bg1 = (const float*)d_in[7];
    const float* Wg2 = (const float*)d_in[8];  const float* bg2 = (const float*)d_in[9];
    const float* Wg3 = (const float*)d_in[10]; const float* bg3 = (const float*)d_in[11];
    const float* Wc1 = (const float*)d_in[12]; const float* bc1 = (const float*)d_in[13];
    const float* Wc2 = (const float*)d_in[14]; const float* bc2 = (const float*)d_in[15];
    const float* Wc3 = (const float*)d_in[16]; const float* bc3 = (const float*)d_in[17];

    int E = in_sizes[2] / 2;
    int P = in_sizes[3];
    const int* src = ei;
    const int* dst = ei + E;

    // dropout keys: split(key(7), 4), partitionable fold-like
    uint32_t dk[4][2];
    for (int j = 0; j < 4; j++) {
        uint32_t a = 0u, b = (uint32_t)j;
        threefry2x32(0u, 7u, a, b);
        dk[j][0] = a; dk[j][1] = b;
    }

    void *p_deg, *p_hs1, *p_agg1, *p_h1, *p_hs2, *p_agg2, *p_h2;
    void *p_hs3, *p_agg3, *p_hp, *p_c1, *p_c2, *p_c3;
    cudaGetSymbolAddress(&p_deg, g_deg);
    cudaGetSymbolAddress(&p_hs1, g_hs1);   cudaGetSymbolAddress(&p_agg1, g_agg1);
    cudaGetSymbolAddress(&p_h1, g_h1);     cudaGetSymbolAddress(&p_hs2, g_hs2);
    cudaGetSymbolAddress(&p_agg2, g_agg2); cudaGetSymbolAddress(&p_h2, g_h2);
    cudaGetSymbolAddress(&p_hs3, g_hs3);   cudaGetSymbolAddress(&p_agg3, g_agg3);
    cudaGetSymbolAddress(&p_hp, g_hp);
    cudaGetSymbolAddress(&p_c1, g_c1);     cudaGetSymbolAddress(&p_c2, g_c2);
    cudaGetSymbolAddress(&p_c3, g_c3);

    cudaStream_t st = 0;
    cudaMemsetAsync(p_deg,  0, NN * sizeof(float), st);
    cudaMemsetAsync(p_agg1, 0, (size_t)NN * FH * sizeof(float), st);
    cudaMemsetAsync(p_agg2, 0, (size_t)NN * FH * sizeof(float), st);
    cudaMemsetAsync(p_agg3, 0, (size_t)NN * FO * sizeof(float), st);
    cudaMemsetAsync(p_hp,   0, (size_t)NN * FO * sizeof(float), st);

    k_deg<<<cdiv(E, 256), 256, 0, st>>>(dst, E);
    k_dis<<<cdiv(NN, 256), 256, 0, st>>>();

    dim3 blk(256);

    // ---- GCN layer 1: hs1 = dis*(x@Wg1) -> agg -> finish(+dropout dk0) ----
    sgemm128<false, false, true><<<dim3(cdiv(NN, 128), FH / 128), blk, 0, st>>>(
        x, Wg1, nullptr, (float*)p_hs1, NN, FIN, FH);
    k_agg128<<<cdiv((long long)E * 32, 256), blk, 0, st>>>(
        (const float*)p_hs1, src, dst, E, (float*)p_agg1);
    k_finish_hid<<<cdiv(NN * FH, 256), blk, 0, st>>>(
        (const float*)p_agg1, (const float*)p_hs1, bg1, (float*)p_h1, dk[0][0], dk[0][1]);

    // ---- GCN layer 2 ----
    sgemm128<false, false, true><<<dim3(cdiv(NN, 128), FH / 128), blk, 0, st>>>(
        (const float*)p_h1, Wg2, nullptr, (float*)p_hs2, NN, FH, FH);
    k_agg128<<<cdiv((long long)E * 32, 256), blk, 0, st>>>(
        (const float*)p_hs2, src, dst, E, (float*)p_agg2);
    k_finish_hid<<<cdiv(NN * FH, 256), blk, 0, st>>>(
        (const float*)p_agg2, (const float*)p_hs2, bg2, (float*)p_h2, dk[1][0], dk[1][1]);

    // ---- GCN layer 3 (N = 40) ----
    sgemm64<false, false, true><<<dim3(cdiv(NN, 64), 1), blk, 0, st>>>(
        (const float*)p_h2, Wg3, nullptr, (float*)p_hs3, NN, FH, FO);
    k_agg40<<<cdiv((long long)E * 10, 256), blk, 0, st>>>(
        (const float*)p_hs3, src, dst, E, (float*)p_agg3);
    k_finish40<<<cdiv(NN * FO, 256), blk, 0, st>>>(
        (const float*)p_agg3, (const float*)p_hs3, bg3);

    // ---- SpMM with partition matrix ----
    k_spmm<<<cdiv((long long)P * 10, 256), blk, 0, st>>>(prow, pcol, pval, P);

    // ---- compensation MLP ----
    sgemm128<true, true, false><<<dim3(cdiv(NN, 128), FC / 128), blk, 0, st>>>(
        omega, Wc1, bc1, (float*)p_c1, NN, FIN, FC);
    k_dropout<<<cdiv(NN * FC, 256), blk, 0, st>>>((float*)p_c1, NN * FC, dk[2][0], dk[2][1]);

    sgemm128<true, true, false><<<dim3(cdiv(NN, 128), FC / 128), blk, 0, st>>>(
        (const float*)p_c1, Wc2, bc2, (float*)p_c2, NN, FC, FC);
    k_dropout<<<cdiv(NN * FC, 256), blk, 0, st>>>((float*)p_c2, NN * FC, dk[3][0], dk[3][1]);

    sgemm64<true, false, false><<<dim3(cdiv(NN, 64), 1), blk, 0, st>>>(
        (const float*)p_c2, Wc3, bc3, (float*)p_c3, NN, FC, FO);

    // ---- combine + log_softmax ----
    k_final<<<cdiv((long long)NN * 32, 256), blk, 0, st>>>((float*)d_out);
}

// round 5
// speedup vs baseline: 1.3009x; 1.0813x over previous
#include <cuda_runtime.h>
#include <cuda_bf16.h>
#include <stdint.h>

#define NN   50000
#define FIN  512
#define FH   128
#define FO   40
#define FC   256
#define MPAD 50048            // 391 * 128
#define MT   391

// ---------------- scratch (device globals; no allocation allowed) ----------
__device__ float g_deg[NN];
__device__ float g_dis[NN];
__device__ float g_hs1[NN * FH];
__device__ float g_agg1[NN * FH];
__device__ float g_hs2[NN * FH];
__device__ float g_agg2[NN * FH];
__device__ float g_h2[NN * FH];
__device__ float g_hs3[NN * FO];
__device__ float g_agg3[NN * FO];
__device__ float g_h3[NN * FO];
__device__ float g_hp[NN * FO];
__device__ float g_c1[NN * FC];
__device__ float g_c2[NN * FC];
__device__ float g_c3[NN * FO];
__device__ __nv_bfloat16 g_abig[(size_t)MPAD * 3 * FIN];   // [Mpad, Kp<=1536]
__device__ __nv_bfloat16 g_wbig[(size_t)FC * 3 * FIN];     // [N<=256, Kp<=1536]

// ---------------- threefry2x32 (JAX-compatible, partitionable) -------------
__host__ __device__ __forceinline__ void threefry2x32(uint32_t k0, uint32_t k1,
                                                      uint32_t& x0, uint32_t& x1) {
    uint32_t ks0 = k0, ks1 = k1, ks2 = k0 ^ k1 ^ 0x1BD11BDAu;
    x0 += ks0; x1 += ks1;
#define TF_RND(r) { x0 += x1; x1 = (x1 << (r)) | (x1 >> (32 - (r))); x1 ^= x0; }
    TF_RND(13) TF_RND(15) TF_RND(26) TF_RND(6)   x0 += ks1; x1 += ks2 + 1u;
    TF_RND(17) TF_RND(29) TF_RND(16) TF_RND(24)  x0 += ks2; x1 += ks0 + 2u;
    TF_RND(13) TF_RND(15) TF_RND(26) TF_RND(6)   x0 += ks0; x1 += ks1 + 3u;
    TF_RND(17) TF_RND(29) TF_RND(16) TF_RND(24)  x0 += ks1; x1 += ks2 + 4u;
    TF_RND(13) TF_RND(15) TF_RND(26) TF_RND(6)   x0 += ks2; x1 += ks0 + 5u;
#undef TF_RND
}

__device__ __forceinline__ bool tf_keep(uint32_t k0, uint32_t k1, uint32_t idx) {
    uint32_t x0 = 0u, x1 = idx;
    threefry2x32(k0, k1, x0, x1);
    return (((x0 ^ x1) >> 31) == 0u);
}

__device__ __forceinline__ void red_add_v4(float* p, float4 v) {
    asm volatile("red.global.add.v4.f32 [%0], {%1, %2, %3, %4};"
                 :: "l"(p), "f"(v.x), "f"(v.y), "f"(v.z), "f"(v.w) : "memory");
}

__device__ __forceinline__ void split_bf16(float a, __nv_bfloat16& h, __nv_bfloat16& l) {
    h = __float2bfloat16(a);
    l = __float2bfloat16(a - __bfloat162float(h));
}

__device__ __forceinline__ uint32_t smem_u32(const void* p) {
    uint32_t a;
    asm("{ .reg .u64 t; cvta.to.shared.u64 t, %1; cvt.u32.u64 %0, t; }" : "=r"(a) : "l"(p));
    return a;
}

__device__ __forceinline__ void ldsm_x4(uint32_t* r, uint32_t addr) {
    asm volatile("ldmatrix.sync.aligned.m8n8.x4.shared.b16 {%0,%1,%2,%3}, [%4];"
                 : "=r"(r[0]), "=r"(r[1]), "=r"(r[2]), "=r"(r[3]) : "r"(addr));
}

__device__ __forceinline__ void mma16816(float* c, const uint32_t* a, const uint32_t* b) {
    asm volatile("mma.sync.aligned.m16n8k16.row.col.f32.bf16.bf16.f32 "
                 "{%0,%1,%2,%3}, {%4,%5,%6,%7}, {%8,%9}, {%0,%1,%2,%3};"
                 : "+f"(c[0]), "+f"(c[1]), "+f"(c[2]), "+f"(c[3])
                 : "r"(a[0]), "r"(a[1]), "r"(a[2]), "r"(a[3]), "r"(b[0]), "r"(b[1]));
}

// ---------------- degree / normalization -----------------------------------
__global__ void k_deg(const int* __restrict__ dst, int E) {
    int i = blockIdx.x * blockDim.x + threadIdx.x;
    if (i < E) atomicAdd(&g_deg[dst[i]], 1.0f);
}
__global__ void k_dis() {
    int i = blockIdx.x * blockDim.x + threadIdx.x;
    if (i < NN) g_dis[i] = rsqrtf(1.0f + g_deg[i]);
}

// ---------------- split conversions ----------------------------------------
// A[M,K] fp32 -> Abig[Mpad, Kp=3K] = [hi | lo | hi], zero pad rows
__global__ void k_splitA(const float* __restrict__ A, __nv_bfloat16* __restrict__ out,
                         int M, int K) {
    int K2 = K >> 1;
    int idx = blockIdx.x * blockDim.x + threadIdx.x;
    if (idx >= MPAD * K2) return;
    int r = idx / K2, kk = (idx - r * K2) * 2;
    __nv_bfloat162 hi2, lo2;
    if (r < M) {
        float2 a = *reinterpret_cast<const float2*>(A + (size_t)r * K + kk);
        __nv_bfloat16 h0, h1, l0, l1;
        split_bf16(a.x, h0, l0);
        split_bf16(a.y, h1, l1);
        hi2 = __halves2bfloat162(h0, h1);
        lo2 = __halves2bfloat162(l0, l1);
    } else {
        __nv_bfloat16 z = __float2bfloat16(0.f);
        hi2 = __halves2bfloat162(z, z); lo2 = hi2;
    }
    size_t base = (size_t)r * (3 * K);
    *reinterpret_cast<__nv_bfloat162*>(out + base + kk)         = hi2;
    *reinterpret_cast<__nv_bfloat162*>(out + base + K + kk)     = lo2;
    *reinterpret_cast<__nv_bfloat162*>(out + base + 2 * K + kk) = hi2;
}

// W[K,N] fp32 -> Wbig[N, 3K] = [hi | hi | lo] (transposed)
__global__ void k_splitW(const float* __restrict__ W, __nv_bfloat16* __restrict__ out,
                         int K, int N) {
    int idx = blockIdx.x * blockDim.x + threadIdx.x;
    if (idx >= K * N) return;
    int k = idx / N, n = idx - k * N;
    __nv_bfloat16 h, l;
    split_bf16(W[(size_t)k * N + n], h, l);
    size_t base = (size_t)n * (3 * K);
    out[base + k] = h;
    out[base + K + k] = h;
    out[base + 2 * K + k] = l;
}

// ---------------- bf16 MMA GEMM: C[M,N] = Abig[Mpad,Kp] @ Wbig[N,Kp]^T ------
// 128x128 block tile, 8 warps (4M x 2N), warp tile 32x64, BK=64, m16n8k16.
template <bool BIAS, bool RELU, bool SCALE>
__global__ void __launch_bounds__(256)
mma_gemm(const __nv_bfloat16* __restrict__ A, const __nv_bfloat16* __restrict__ B,
         const float* __restrict__ bias, float* __restrict__ C,
         int M, int Kp, int N) {
    __shared__ __align__(16) __nv_bfloat16 As[128][72];
    __shared__ __align__(16) __nv_bfloat16 Bs[128][72];

    int tid = threadIdx.x, wid = tid >> 5, lane = tid & 31;
    int bm = blockIdx.x * 128, bn = blockIdx.y * 128;
    int wm = (wid & 3) << 5;      // 0,32,64,96
    int wn = (wid >> 2) << 6;     // 0,64

    float acc[2][8][4];
#pragma unroll
    for (int i = 0; i < 2; i++)
#pragma unroll
        for (int j = 0; j < 8; j++)
#pragma unroll
            for (int q = 0; q < 4; q++) acc[i][j][q] = 0.0f;

    int mat = lane >> 3, r8 = lane & 7;

    for (int k0 = 0; k0 < Kp; k0 += 64) {
        // load tiles: 128 rows x 64 bf16 = 128 x 8 uint4 each
        for (int i = tid; i < 128 * 8; i += 256) {
            int r = i >> 3, c = i & 7;
            uint4 va = *reinterpret_cast<const uint4*>(A + (size_t)(bm + r) * Kp + k0 + c * 8);
            *reinterpret_cast<uint4*>(&As[r][c * 8]) = va;
            uint4 vb = *reinterpret_cast<const uint4*>(B + (size_t)(bn + r) * Kp + k0 + c * 8);
            *reinterpret_cast<uint4*>(&Bs[r][c * 8]) = vb;
        }
        __syncthreads();

#pragma unroll
        for (int kk = 0; kk < 64; kk += 16) {
            uint32_t a[2][4];
#pragma unroll
            for (int mf = 0; mf < 2; mf++) {
                // matrices in order a0..a3: (m0-7,k0),(m8-15,k0),(m0-7,k8),(m8-15,k8)
                uint32_t addr = smem_u32(
                    &As[wm + mf * 16 + ((mat & 1) << 3) + r8][kk + ((mat >> 1) << 3)]);
                ldsm_x4(a[mf], addr);
            }
            uint32_t b[8][2];
#pragma unroll
            for (int nf2 = 0; nf2 < 4; nf2++) {
                // matrices: (n0-7,k0),(n0-7,k8),(n8-15,k0),(n8-15,k8)
                uint32_t addr = smem_u32(
                    &Bs[wn + nf2 * 16 + ((mat >> 1) << 3) + r8][kk + ((mat & 1) << 3)]);
                uint32_t t[4];
                ldsm_x4(t, addr);
                b[nf2 * 2][0] = t[0]; b[nf2 * 2][1] = t[1];
                b[nf2 * 2 + 1][0] = t[2]; b[nf2 * 2 + 1][1] = t[3];
            }
#pragma unroll
            for (int mf = 0; mf < 2; mf++)
#pragma unroll
                for (int nf = 0; nf < 8; nf++)
                    mma16816(acc[mf][nf], a[mf], b[nf]);
        }
        __syncthreads();
    }

    // epilogue: thread holds C[g + 8h][2tg..2tg+1] per fragment
    int g = lane >> 2, tg = lane & 3;
#pragma unroll
    for (int mf = 0; mf < 2; mf++) {
#pragma unroll
        for (int half = 0; half < 2; half++) {
            int r = bm + wm + mf * 16 + g + half * 8;
            if (r >= M) continue;
            float sc = SCALE ? g_dis[r] : 1.0f;
#pragma unroll
            for (int nf = 0; nf < 8; nf++) {
                int c = bn + wn + nf * 8 + tg * 2;
                float v0 = acc[mf][nf][half * 2 + 0];
                float v1 = acc[mf][nf][half * 2 + 1];
                if (BIAS) { v0 += bias[c]; v1 += bias[c + 1]; }
                if (RELU) { v0 = fmaxf(v0, 0.0f); v1 = fmaxf(v1, 0.0f); }
                if (SCALE) { v0 *= sc; v1 *= sc; }
                *reinterpret_cast<float2*>(&C[(size_t)r * N + c]) = make_float2(v0, v1);
            }
        }
    }
}

// ---------------- SGEMM 64x64x16 fp32 (for N=40 layers) --------------------
template <bool BIAS, bool RELU, bool SCALE>
__global__ void sgemm64(const float* __restrict__ A, const float* __restrict__ W,
                        const float* __restrict__ bias, float* __restrict__ C,
                        int M, int K, int N) {
    const int BM = 64, BN = 64, BK = 16;
    __shared__ float As[BK][BM + 4];
    __shared__ float Ws[BK][BN];

    int tid = threadIdx.x;
    int bm = blockIdx.x * BM, bn = blockIdx.y * BN;
    int tx = tid & 15, ty = tid >> 4;
    int arow = tid >> 2, acol4 = tid & 3;
    int wrow = tid >> 4, wcol4 = tid & 15;

    float acc[4][4];
#pragma unroll
    for (int i = 0; i < 4; i++)
#pragma unroll
        for (int j = 0; j < 4; j++) acc[i][j] = 0.0f;

    for (int k0 = 0; k0 < K; k0 += BK) {
        float4 av = make_float4(0.f, 0.f, 0.f, 0.f);
        int gr = bm + arow;
        if (gr < M)
            av = *reinterpret_cast<const float4*>(&A[(size_t)gr * K + k0 + acol4 * 4]);
        As[acol4 * 4 + 0][arow] = av.x;
        As[acol4 * 4 + 1][arow] = av.y;
        As[acol4 * 4 + 2][arow] = av.z;
        As[acol4 * 4 + 3][arow] = av.w;

        float4 wv = make_float4(0.f, 0.f, 0.f, 0.f);
        int gc = bn + wcol4 * 4;
        if (gc < N)
            wv = *reinterpret_cast<const float4*>(&W[(size_t)(k0 + wrow) * N + gc]);
        Ws[wrow][wcol4 * 4 + 0] = wv.x;
        Ws[wrow][wcol4 * 4 + 1] = wv.y;
        Ws[wrow][wcol4 * 4 + 2] = wv.z;
        Ws[wrow][wcol4 * 4 + 3] = wv.w;

        __syncthreads();
#pragma unroll
        for (int k = 0; k < BK; k++) {
            float a[4], w[4];
#pragma unroll
            for (int i = 0; i < 4; i++) a[i] = As[k][ty * 4 + i];
#pragma unroll
            for (int j = 0; j < 4; j++) w[j] = Ws[k][tx * 4 + j];
#pragma unroll
            for (int i = 0; i < 4; i++)
#pragma unroll
                for (int j = 0; j < 4; j++) acc[i][j] = fmaf(a[i], w[j], acc[i][j]);
        }
        __syncthreads();
    }

#pragma unroll
    for (int i = 0; i < 4; i++) {
        int r = bm + ty * 4 + i;
        if (r >= M) continue;
        float sc = SCALE ? g_dis[r] : 1.0f;
#pragma unroll
        for (int j = 0; j < 4; j++) {
            int c = bn + tx * 4 + j;
            if (c >= N) continue;
            float v = acc[i][j];
            if (BIAS) v += bias[c];
            if (RELU) v = fmaxf(v, 0.0f);
            if (SCALE) v *= sc;
            C[(size_t)r * N + c] = v;
        }
    }
}

// ---------------- edge aggregation -----------------------------------------
__global__ void k_agg128(const float* __restrict__ hs, const int* __restrict__ src,
                         const int* __restrict__ dst, int E, float* __restrict__ agg) {
    long long t = (long long)blockIdx.x * blockDim.x + threadIdx.x;
    long long total = (long long)E * 32;
    if (t >= total) return;
    int e = (int)(t >> 5);
    int q = (int)(t & 31);
    int s = __ldg(&src[e]), d = __ldg(&dst[e]);
    float4 v = __ldg(reinterpret_cast<const float4*>(hs) + (size_t)s * 32 + q);
    red_add_v4(agg + ((size_t)d * 32 + q) * 4, v);
}

__global__ void k_agg40(const float* __restrict__ hs, const int* __restrict__ src,
                        const int* __restrict__ dst, int E, float* __restrict__ agg) {
    long long t = (long long)blockIdx.x * blockDim.x + threadIdx.x;
    long long total = (long long)E * 10;
    if (t >= total) return;
    int e = (int)(t / 10);
    int q = (int)(t - (long long)e * 10);
    int s = __ldg(&src[e]), d = __ldg(&dst[e]);
    float4 v = __ldg(reinterpret_cast<const float4*>(hs) + (size_t)s * 10 + q);
    red_add_v4(agg + ((size_t)d * 10 + q) * 4, v);
}

// ---------------- finish layer1: relu+dropout -> split bf16 into Abig ------
__global__ void k_finish_split(const float* __restrict__ agg, const float* __restrict__ hs,
                               const float* __restrict__ b, __nv_bfloat16* __restrict__ out,
                               uint32_t k0, uint32_t k1) {
    int e = blockIdx.x * blockDim.x + threadIdx.x;
    if (e >= MPAD * FH) return;
    int r = e >> 7, c = e & (FH - 1);
    __nv_bfloat16 h = __float2bfloat16(0.f), l = h;
    if (r < NN) {
        float v = g_dis[r] * (agg[e] + hs[e]) + b[c];
        v = fmaxf(v, 0.0f);
        v = tf_keep(k0, k1, (uint32_t)e) ? 2.0f * v : 0.0f;
        split_bf16(v, h, l);
    }
    size_t base = (size_t)r * (3 * FH);
    out[base + c] = h;
    out[base + FH + c] = l;
    out[base + 2 * FH + c] = h;
}

// ---------------- finish layer2: relu+dropout -> fp32 h2 -------------------
__global__ void k_finish_hid(const float* __restrict__ agg, const float* __restrict__ hs,
                             const float* __restrict__ b, float* __restrict__ out,
                             uint32_t k0, uint32_t k1) {
    int e = blockIdx.x * blockDim.x + threadIdx.x;
    if (e >= NN * FH) return;
    int r = e >> 7, c = e & (FH - 1);
    float v = g_dis[r] * (agg[e] + hs[e]) + b[c];
    v = fmaxf(v, 0.0f);
    out[e] = tf_keep(k0, k1, (uint32_t)e) ? 2.0f * v : 0.0f;
}

// ---------------- finish output GCN layer (F = 40) -------------------------
__global__ void k_finish40(const float* __restrict__ agg, const float* __restrict__ hs,
                           const float* __restrict__ b) {
    int e = blockIdx.x * blockDim.x + threadIdx.x;
    if (e >= NN * FO) return;
    int r = e / FO, c = e - r * FO;
    g_h3[e] = g_dis[r] * (agg[e] + hs[e]) + b[c];
}

// ---------------- dropout -> split bf16 into Abig (comp path) --------------
__global__ void k_dropout_split(const float* __restrict__ in, __nv_bfloat16* __restrict__ out,
                                uint32_t k0, uint32_t k1) {
    int e = blockIdx.x * blockDim.x + threadIdx.x;
    if (e >= MPAD * FC) return;
    int r = e >> 8, c = e & (FC - 1);
    __nv_bfloat16 h = __float2bfloat16(0.f), l = h;
    if (r < NN) {
        float v = tf_keep(k0, k1, (uint32_t)e) ? 2.0f * in[e] : 0.0f;
        split_bf16(v, h, l);
    }
    size_t base = (size_t)r * (3 * FC);
    out[base + c] = h;
    out[base + FC + c] = l;
    out[base + 2 * FC + c] = h;
}

// ---------------- dropout (fp32 in place) -----------------------------------
__global__ void k_dropout(float* __restrict__ buf, int S, uint32_t k0, uint32_t k1) {
    int e = blockIdx.x * blockDim.x + threadIdx.x;
    if (e >= S) return;
    float a = buf[e];
    buf[e] = tf_keep(k0, k1, (uint32_t)e) ? 2.0f * a : 0.0f;
}

// ---------------- SpMM -------------------------------------------------------
__global__ void k_spmm(const int* __restrict__ rows, const int* __restrict__ cols,
                       const float* __restrict__ vals, int P) {
    long long t = (long long)blockIdx.x * blockDim.x + threadIdx.x;
    long long total = (long long)P * 10;
    if (t >= total) return;
    int e = (int)(t / 10);
    int q = (int)(t - (long long)e * 10);
    int r = __ldg(&rows[e]), c = __ldg(&cols[e]);
    float val = __ldg(&vals[e]);
    float4 v = __ldg(reinterpret_cast<const float4*>(g_h3) + (size_t)c * 10 + q);
    v.x *= val; v.y *= val; v.z *= val; v.w *= val;
    red_add_v4(g_hp + ((size_t)r * 10 + q) * 4, v);
}

// ---------------- final: z = hp*(1+c3); log_softmax -------------------------
__global__ void k_final(float* __restrict__ out) {
    int gt = blockIdx.x * blockDim.x + threadIdx.x;
    int w = gt >> 5;
    int lane = gt & 31;
    if (w >= NN) return;

    const float NEG_INF = __int_as_float(0xff800000);
    int c0 = lane, c1 = lane + 32;
    size_t base = (size_t)w * FO;

    float z0 = g_hp[base + c0] * (1.0f + g_c3[base + c0]);
    float z1 = (c1 < FO) ? g_hp[base + c1] * (1.0f + g_c3[base + c1]) : NEG_INF;

    float m = fmaxf(z0, z1);
#pragma unroll
    for (int off = 16; off > 0; off >>= 1)
        m = fmaxf(m, __shfl_xor_sync(0xffffffffu, m, off));

    float s = expf(z0 - m) + ((c1 < FO) ? expf(z1 - m) : 0.0f);
#pragma unroll
    for (int off = 16; off > 0; off >>= 1)
        s += __shfl_xor_sync(0xffffffffu, s, off);

    float lse = logf(s) + m;
    out[base + c0] = z0 - lse;
    if (c1 < FO) out[base + c1] = z1 - lse;
}

// ---------------- host launcher ---------------------------------------------
static inline int cdiv(long long a, int b) { return (int)((a + b - 1) / b); }

extern "C" void kernel_launch(void* const* d_in, const int* in_sizes, int n_in,
                              void* d_out, int out_size) {
    const float* x     = (const float*)d_in[0];
    const float* omega = (const float*)d_in[1];
    const int*   ei    = (const int*)d_in[2];
    const int*   prow  = (const int*)d_in[3];
    const int*   pcol  = (const int*)d_in[4];
    const float* pval  = (const float*)d_in[5];
    const float* Wg1 = (const float*)d_in[6];  const float* bg1 = (const float*)d_in[7];
    const float* Wg2 = (const float*)d_in[8];  const float* bg2 = (const float*)d_in[9];
    const float* Wg3 = (const float*)d_in[10]; const float* bg3 = (const float*)d_in[11];
    const float* Wc1 = (const float*)d_in[12]; const float* bc1 = (const float*)d_in[13];
    const float* Wc2 = (const float*)d_in[14]; const float* bc2 = (const float*)d_in[15];
    const float* Wc3 = (const float*)d_in[16]; const float* bc3 = (const float*)d_in[17];

    int E = in_sizes[2] / 2;
    int P = in_sizes[3];
    const int* src = ei;
    const int* dst = ei + E;

    uint32_t dk[4][2];
    for (int j = 0; j < 4; j++) {
        uint32_t a = 0u, b = (uint32_t)j;
        threefry2x32(0u, 7u, a, b);
        dk[j][0] = a; dk[j][1] = b;
    }

    void *p_deg, *p_hs1, *p_agg1, *p_hs2, *p_agg2, *p_h2;
    void *p_hs3, *p_agg3, *p_hp, *p_c1, *p_c2, *p_c3, *p_abig, *p_wbig;
    cudaGetSymbolAddress(&p_deg, g_deg);
    cudaGetSymbolAddress(&p_hs1, g_hs1);   cudaGetSymbolAddress(&p_agg1, g_agg1);
    cudaGetSymbolAddress(&p_hs2, g_hs2);   cudaGetSymbolAddress(&p_agg2, g_agg2);
    cudaGetSymbolAddress(&p_h2, g_h2);
    cudaGetSymbolAddress(&p_hs3, g_hs3);   cudaGetSymbolAddress(&p_agg3, g_agg3);
    cudaGetSymbolAddress(&p_hp, g_hp);
    cudaGetSymbolAddress(&p_c1, g_c1);     cudaGetSymbolAddress(&p_c2, g_c2);
    cudaGetSymbolAddress(&p_c3, g_c3);
    cudaGetSymbolAddress(&p_abig, g_abig); cudaGetSymbolAddress(&p_wbig, g_wbig);

    __nv_bfloat16* abig = (__nv_bfloat16*)p_abig;
    __nv_bfloat16* wbig = (__nv_bfloat16*)p_wbig;

    cudaStream_t st = 0;
    cudaMemsetAsync(p_deg,  0, NN * sizeof(float), st);
    cudaMemsetAsync(p_agg1, 0, (size_t)NN * FH * sizeof(float), st);
    cudaMemsetAsync(p_agg2, 0, (size_t)NN * FH * sizeof(float), st);
    cudaMemsetAsync(p_agg3, 0, (size_t)NN * FO * sizeof(float), st);
    cudaMemsetAsync(p_hp,   0, (size_t)NN * FO * sizeof(float), st);

    k_deg<<<cdiv(E, 256), 256, 0, st>>>(dst, E);
    k_dis<<<cdiv(NN, 256), 256, 0, st>>>();

    dim3 blk(256);

    // ---- GCN layer 1: Abig=[xh|xl|xh], Wbig=[Wh|Wh|Wl]^T -> hs1=dis*(x@Wg1)
    k_splitA<<<cdiv((long long)MPAD * (FIN / 2), 256), blk, 0, st>>>(x, abig, NN, FIN);
    k_splitW<<<cdiv(FIN * FH, 256), blk, 0, st>>>(Wg1, wbig, FIN, FH);
    mma_gemm<false, false, true><<<dim3(MT, 1), blk, 0, st>>>(
        abig, wbig, nullptr, (float*)p_hs1, NN, 3 * FIN, FH);
    k_agg128<<<cdiv((long long)E * 32, 256), blk, 0, st>>>(
        (const float*)p_hs1, src, dst, E, (float*)p_agg1);
    k_finish_split<<<cdiv(MPAD * FH, 256), blk, 0, st>>>(
        (const float*)p_agg1, (const float*)p_hs1, bg1, abig, dk[0][0], dk[0][1]);

    // ---- GCN layer 2 (Kp = 384) ----
    k_splitW<<<cdiv(FH * FH, 256), blk, 0, st>>>(Wg2, wbig, FH, FH);
    mma_gemm<false, false, true><<<dim3(MT, 1), blk, 0, st>>>(
        abig, wbig, nullptr, (float*)p_hs2, NN, 3 * FH, FH);
    k_agg128<<<cdiv((long long)E * 32, 256), blk, 0, st>>>(
        (const float*)p_hs2, src, dst, E, (float*)p_agg2);
    k_finish_hid<<<cdiv(NN * FH, 256), blk, 0, st>>>(
        (const float*)p_agg2, (const float*)p_hs2, bg2, (float*)p_h2, dk[1][0], dk[1][1]);

    // ---- GCN layer 3 (N = 40, fp32) ----
    sgemm64<false, false, true><<<dim3(cdiv(NN, 64), 1), blk, 0, st>>>(
        (const float*)p_h2, Wg3, nullptr, (float*)p_hs3, NN, FH, FO);
    k_agg40<<<cdiv((long long)E * 10, 256), blk, 0, st>>>(
        (const float*)p_hs3, src, dst, E, (float*)p_agg3);
    k_finish40<<<cdiv(NN * FO, 256), blk, 0, st>>>(
        (const float*)p_agg3, (const float*)p_hs3, bg3);

    // ---- SpMM with partition matrix ----
    k_spmm<<<cdiv((long long)P * 10, 256), blk, 0, st>>>(prow, pcol, pval, P);

    // ---- compensation MLP ----
    k_splitA<<<cdiv((long long)MPAD * (FIN / 2), 256), blk, 0, st>>>(omega, abig, NN, FIN);
    k_splitW<<<cdiv(FIN * FC, 256), blk, 0, st>>>(Wc1, wbig, FIN, FC);
    mma_gemm<true, true, false><<<dim3(MT, 2), blk, 0, st>>>(
        abig, wbig, bc1, (float*)p_c1, NN, 3 * FIN, FC);
    k_dropout_split<<<cdiv(MPAD * FC, 256), blk, 0, st>>>(
        (const float*)p_c1, abig, dk[2][0], dk[2][1]);

    k_splitW<<<cdiv(FC * FC, 256), blk, 0, st>>>(Wc2, wbig, FC, FC);
    mma_gemm<true, true, false><<<dim3(MT, 2), blk, 0, st>>>(
        abig, wbig, bc2, (float*)p_c2, NN, 3 * FC, FC);
    k_dropout<<<cdiv(NN * FC, 256), blk, 0, st>>>((float*)p_c2, NN * FC, dk[3][0], dk[3][1]);

    sgemm64<true, false, false><<<dim3(cdiv(NN, 64), 1), blk, 0, st>>>(
        (const float*)p_c2, Wc3, bc3, (float*)p_c3, NN, FC, FO);

    // ---- combine + log_softmax ----
    k_final<<<cdiv((long long)NN * 32, 256), blk, 0, st>>>((float*)d_out);
}

// round 6
// speedup vs baseline: 1.6600x; 1.2760x over previous
#include <cuda_runtime.h>
#include <cuda_bf16.h>
#include <stdint.h>

#define NN   50000
#define FIN  512
#define FH   128
#define FO   40
#define FC   256
#define MPAD 50048            // 391 * 128
#define MT   391

// ---------------- scratch (device globals; no allocation allowed) ----------
__device__ float g_deg[NN];
__device__ float g_dis[NN];
__device__ float g_hs1[NN * FH];
__device__ float g_agg1[NN * FH];
__device__ float g_hs2[NN * FH];
__device__ float g_agg2[NN * FH];
__device__ float g_h2[NN * FH];
__device__ float g_hs3[NN * FO];
__device__ float g_agg3[NN * FO];
__device__ float g_h3[NN * FO];
__device__ float g_hp[NN * FO];
__device__ float g_c1[NN * FC];
__device__ float g_c2[NN * FC];
__device__ float g_c3[NN * FO];
__device__ __nv_bfloat16 g_abig[(size_t)MPAD * 3 * FIN];   // [Mpad, Kp<=1536]
__device__ __nv_bfloat16 g_wbig[(size_t)FC * 3 * FIN];     // [N<=256, Kp<=1536]

// ---------------- threefry2x32 (JAX-compatible, partitionable) -------------
__host__ __device__ __forceinline__ void threefry2x32(uint32_t k0, uint32_t k1,
                                                      uint32_t& x0, uint32_t& x1) {
    uint32_t ks0 = k0, ks1 = k1, ks2 = k0 ^ k1 ^ 0x1BD11BDAu;
    x0 += ks0; x1 += ks1;
#define TF_RND(r) { x0 += x1; x1 = (x1 << (r)) | (x1 >> (32 - (r))); x1 ^= x0; }
    TF_RND(13) TF_RND(15) TF_RND(26) TF_RND(6)   x0 += ks1; x1 += ks2 + 1u;
    TF_RND(17) TF_RND(29) TF_RND(16) TF_RND(24)  x0 += ks2; x1 += ks0 + 2u;
    TF_RND(13) TF_RND(15) TF_RND(26) TF_RND(6)   x0 += ks0; x1 += ks1 + 3u;
    TF_RND(17) TF_RND(29) TF_RND(16) TF_RND(24)  x0 += ks1; x1 += ks2 + 4u;
    TF_RND(13) TF_RND(15) TF_RND(26) TF_RND(6)   x0 += ks2; x1 += ks0 + 5u;
#undef TF_RND
}

__device__ __forceinline__ bool tf_keep(uint32_t k0, uint32_t k1, uint32_t idx) {
    uint32_t x0 = 0u, x1 = idx;
    threefry2x32(k0, k1, x0, x1);
    return (((x0 ^ x1) >> 31) == 0u);
}

__device__ __forceinline__ void red_add_v4(float* p, float4 v) {
    asm volatile("red.global.add.v4.f32 [%0], {%1, %2, %3, %4};"
                 :: "l"(p), "f"(v.x), "f"(v.y), "f"(v.z), "f"(v.w) : "memory");
}

__device__ __forceinline__ void split_bf16(float a, __nv_bfloat16& h, __nv_bfloat16& l) {
    h = __float2bfloat16(a);
    l = __float2bfloat16(a - __bfloat162float(h));
}

__device__ __forceinline__ uint32_t smem_u32(const void* p) {
    uint32_t a;
    asm("{ .reg .u64 t; cvta.to.shared.u64 t, %1; cvt.u32.u64 %0, t; }" : "=r"(a) : "l"(p));
    return a;
}

__device__ __forceinline__ void ldsm_x4(uint32_t* r, uint32_t addr) {
    asm volatile("ldmatrix.sync.aligned.m8n8.x4.shared.b16 {%0,%1,%2,%3}, [%4];"
                 : "=r"(r[0]), "=r"(r[1]), "=r"(r[2]), "=r"(r[3]) : "r"(addr));
}

__device__ __forceinline__ void mma16816(float* c, const uint32_t* a, const uint32_t* b) {
    asm volatile("mma.sync.aligned.m16n8k16.row.col.f32.bf16.bf16.f32 "
                 "{%0,%1,%2,%3}, {%4,%5,%6,%7}, {%8,%9}, {%0,%1,%2,%3};"
                 : "+f"(c[0]), "+f"(c[1]), "+f"(c[2]), "+f"(c[3])
                 : "r"(a[0]), "r"(a[1]), "r"(a[2]), "r"(a[3]), "r"(b[0]), "r"(b[1]));
}

__device__ __forceinline__ void cp_async16(uint32_t saddr, const void* gaddr) {
    asm volatile("cp.async.cg.shared.global [%0], [%1], 16;" :: "r"(saddr), "l"(gaddr));
}
#define CP_COMMIT() asm volatile("cp.async.commit_group;" ::: "memory")
#define CP_WAIT(n)  asm volatile("cp.async.wait_group %0;" :: "n"(n) : "memory")

// ---------------- degree / normalization -----------------------------------
__global__ void k_deg(const int* __restrict__ dst, int E) {
    int i = blockIdx.x * blockDim.x + threadIdx.x;
    if (i < E) atomicAdd(&g_deg[dst[i]], 1.0f);
}
__global__ void k_dis() {
    int i = blockIdx.x * blockDim.x + threadIdx.x;
    if (i < NN) g_dis[i] = rsqrtf(1.0f + g_deg[i]);
}

// ---------------- split conversions ----------------------------------------
__global__ void k_splitA(const float* __restrict__ A, __nv_bfloat16* __restrict__ out,
                         int M, int K) {
    int K2 = K >> 1;
    int idx = blockIdx.x * blockDim.x + threadIdx.x;
    if (idx >= MPAD * K2) return;
    int r = idx / K2, kk = (idx - r * K2) * 2;
    __nv_bfloat162 hi2, lo2;
    if (r < M) {
        float2 a = *reinterpret_cast<const float2*>(A + (size_t)r * K + kk);
        __nv_bfloat16 h0, h1, l0, l1;
        split_bf16(a.x, h0, l0);
        split_bf16(a.y, h1, l1);
        hi2 = __halves2bfloat162(h0, h1);
        lo2 = __halves2bfloat162(l0, l1);
    } else {
        __nv_bfloat16 z = __float2bfloat16(0.f);
        hi2 = __halves2bfloat162(z, z); lo2 = hi2;
    }
    size_t base = (size_t)r * (3 * K);
    *reinterpret_cast<__nv_bfloat162*>(out + base + kk)         = hi2;
    *reinterpret_cast<__nv_bfloat162*>(out + base + K + kk)     = lo2;
    *reinterpret_cast<__nv_bfloat162*>(out + base + 2 * K + kk) = hi2;
}

__global__ void k_splitW(const float* __restrict__ W, __nv_bfloat16* __restrict__ out,
                         int K, int N) {
    int idx = blockIdx.x * blockDim.x + threadIdx.x;
    if (idx >= K * N) return;
    int k = idx / N, n = idx - k * N;
    __nv_bfloat16 h, l;
    split_bf16(W[(size_t)k * N + n], h, l);
    size_t base = (size_t)n * (3 * K);
    out[base + k] = h;
    out[base + K + k] = h;
    out[base + 2 * K + k] = l;
}

// ---------------- bf16 MMA GEMM (cp.async double-buffered) -----------------
// C[M,N] = Abig[Mpad,Kp] @ Wbig[N,Kp]^T; 128x128 tile, 8 warps, BK=64.
template <bool BIAS, bool RELU, bool SCALE>
__global__ void __launch_bounds__(256)
mma_gemm(const __nv_bfloat16* __restrict__ A, const __nv_bfloat16* __restrict__ B,
         const float* __restrict__ bias, float* __restrict__ C,
         int M, int Kp, int N) {
    __shared__ __align__(16) __nv_bfloat16 As[2][128][72];
    __shared__ __align__(16) __nv_bfloat16 Bs[2][128][72];

    int tid = threadIdx.x, wid = tid >> 5, lane = tid & 31;
    int bm = blockIdx.x * 128, bn = blockIdx.y * 128;
    int wm = (wid & 3) << 5;      // 0,32,64,96
    int wn = (wid >> 2) << 6;     // 0,64

    float acc[2][8][4];
#pragma unroll
    for (int i = 0; i < 2; i++)
#pragma unroll
        for (int j = 0; j < 8; j++)
#pragma unroll
            for (int q = 0; q < 4; q++) acc[i][j][q] = 0.0f;

    int mat = lane >> 3, r8 = lane & 7;
    int nT = Kp >> 6;

    // loader indices: 256 threads x 4 iters cover 128 rows x 8 chunks (x2 arrays)
    auto load_tile = [&](int t, int buf) {
        int k0 = t << 6;
#pragma unroll
        for (int i = 0; i < 4; i++) {
            int idx = tid + i * 256;
            int r = idx >> 3, c = idx & 7;
            cp_async16(smem_u32(&As[buf][r][c * 8]),
                       A + (size_t)(bm + r) * Kp + k0 + c * 8);
            cp_async16(smem_u32(&Bs[buf][r][c * 8]),
                       B + (size_t)(bn + r) * Kp + k0 + c * 8);
        }
        CP_COMMIT();
    };

    load_tile(0, 0);

    for (int t = 0; t < nT; t++) {
        int cur = t & 1;
        if (t + 1 < nT) {
            load_tile(t + 1, cur ^ 1);
            CP_WAIT(1);
        } else {
            CP_WAIT(0);
        }
        __syncthreads();

#pragma unroll
        for (int kk = 0; kk < 64; kk += 16) {
            uint32_t a[2][4];
#pragma unroll
            for (int mf = 0; mf < 2; mf++) {
                uint32_t addr = smem_u32(
                    &As[cur][wm + mf * 16 + ((mat & 1) << 3) + r8][kk + ((mat >> 1) << 3)]);
                ldsm_x4(a[mf], addr);
            }
            uint32_t b[8][2];
#pragma unroll
            for (int nf2 = 0; nf2 < 4; nf2++) {
                uint32_t addr = smem_u32(
                    &Bs[cur][wn + nf2 * 16 + ((mat >> 1) << 3) + r8][kk + ((mat & 1) << 3)]);
                uint32_t tr[4];
                ldsm_x4(tr, addr);
                b[nf2 * 2][0] = tr[0]; b[nf2 * 2][1] = tr[1];
                b[nf2 * 2 + 1][0] = tr[2]; b[nf2 * 2 + 1][1] = tr[3];
            }
#pragma unroll
            for (int mf = 0; mf < 2; mf++)
#pragma unroll
                for (int nf = 0; nf < 8; nf++)
                    mma16816(acc[mf][nf], a[mf], b[nf]);
        }
        __syncthreads();
    }

    // epilogue
    int g = lane >> 2, tg = lane & 3;
#pragma unroll
    for (int mf = 0; mf < 2; mf++) {
#pragma unroll
        for (int half = 0; half < 2; half++) {
            int r = bm + wm + mf * 16 + g + half * 8;
            if (r >= M) continue;
            float sc = SCALE ? g_dis[r] : 1.0f;
#pragma unroll
            for (int nf = 0; nf < 8; nf++) {
                int c = bn + wn + nf * 8 + tg * 2;
                float v0 = acc[mf][nf][half * 2 + 0];
                float v1 = acc[mf][nf][half * 2 + 1];
                if (BIAS) { v0 += bias[c]; v1 += bias[c + 1]; }
                if (RELU) { v0 = fmaxf(v0, 0.0f); v1 = fmaxf(v1, 0.0f); }
                if (SCALE) { v0 *= sc; v1 *= sc; }
                *reinterpret_cast<float2*>(&C[(size_t)r * N + c]) = make_float2(v0, v1);
            }
        }
    }
}

// ---------------- SGEMM 64x64x16 fp32 (for N=40 layers) --------------------
template <bool BIAS, bool RELU, bool SCALE>
__global__ void sgemm64(const float* __restrict__ A, const float* __restrict__ W,
                        const float* __restrict__ bias, float* __restrict__ C,
                        int M, int K, int N) {
    const int BM = 64, BN = 64, BK = 16;
    __shared__ float As[BK][BM + 4];
    __shared__ float Ws[BK][BN];

    int tid = threadIdx.x;
    int bm = blockIdx.x * BM, bn = blockIdx.y * BN;
    int tx = tid & 15, ty = tid >> 4;
    int arow = tid >> 2, acol4 = tid & 3;
    int wrow = tid >> 4, wcol4 = tid & 15;

    float acc[4][4];
#pragma unroll
    for (int i = 0; i < 4; i++)
#pragma unroll
        for (int j = 0; j < 4; j++) acc[i][j] = 0.0f;

    for (int k0 = 0; k0 < K; k0 += BK) {
        float4 av = make_float4(0.f, 0.f, 0.f, 0.f);
        int gr = bm + arow;
        if (gr < M)
            av = *reinterpret_cast<const float4*>(&A[(size_t)gr * K + k0 + acol4 * 4]);
        As[acol4 * 4 + 0][arow] = av.x;
        As[acol4 * 4 + 1][arow] = av.y;
        As[acol4 * 4 + 2][arow] = av.z;
        As[acol4 * 4 + 3][arow] = av.w;

        float4 wv = make_float4(0.f, 0.f, 0.f, 0.f);
        int gc = bn + wcol4 * 4;
        if (gc < N)
            wv = *reinterpret_cast<const float4*>(&W[(size_t)(k0 + wrow) * N + gc]);
        Ws[wrow][wcol4 * 4 + 0] = wv.x;
        Ws[wrow][wcol4 * 4 + 1] = wv.y;
        Ws[wrow][wcol4 * 4 + 2] = wv.z;
        Ws[wrow][wcol4 * 4 + 3] = wv.w;

        __syncthreads();
#pragma unroll
        for (int k = 0; k < BK; k++) {
            float a[4], w[4];
#pragma unroll
            for (int i = 0; i < 4; i++) a[i] = As[k][ty * 4 + i];
#pragma unroll
            for (int j = 0; j < 4; j++) w[j] = Ws[k][tx * 4 + j];
#pragma unroll
            for (int i = 0; i < 4; i++)
#pragma unroll
                for (int j = 0; j < 4; j++) acc[i][j] = fmaf(a[i], w[j], acc[i][j]);
        }
        __syncthreads();
    }

#pragma unroll
    for (int i = 0; i < 4; i++) {
        int r = bm + ty * 4 + i;
        if (r >= M) continue;
        float sc = SCALE ? g_dis[r] : 1.0f;
#pragma unroll
        for (int j = 0; j < 4; j++) {
            int c = bn + tx * 4 + j;
            if (c >= N) continue;
            float v = acc[i][j];
            if (BIAS) v += bias[c];
            if (RELU) v = fmaxf(v, 0.0f);
            if (SCALE) v *= sc;
            C[(size_t)r * N + c] = v;
        }
    }
}

// ---------------- edge aggregation -----------------------------------------
__global__ void k_agg128(const float* __restrict__ hs, const int* __restrict__ src,
                         const int* __restrict__ dst, int E, float* __restrict__ agg) {
    long long t = (long long)blockIdx.x * blockDim.x + threadIdx.x;
    long long total = (long long)E * 32;
    if (t >= total) return;
    int e = (int)(t >> 5);
    int q = (int)(t & 31);
    int s = __ldg(&src[e]), d = __ldg(&dst[e]);
    float4 v = __ldg(reinterpret_cast<const float4*>(hs) + (size_t)s * 32 + q);
    red_add_v4(agg + ((size_t)d * 32 + q) * 4, v);
}

__global__ void k_agg40(const float* __restrict__ hs, const int* __restrict__ src,
                        const int* __restrict__ dst, int E, float* __restrict__ agg) {
    long long t = (long long)blockIdx.x * blockDim.x + threadIdx.x;
    long long total = (long long)E * 10;
    if (t >= total) return;
    int e = (int)(t / 10);
    int q = (int)(t - (long long)e * 10);
    int s = __ldg(&src[e]), d = __ldg(&dst[e]);
    float4 v = __ldg(reinterpret_cast<const float4*>(hs) + (size_t)s * 10 + q);
    red_add_v4(agg + ((size_t)d * 10 + q) * 4, v);
}

// ---------------- finish layer1: relu+dropout -> split bf16 into Abig ------
__global__ void k_finish_split(const float* __restrict__ agg, const float* __restrict__ hs,
                               const float* __restrict__ b, __nv_bfloat16* __restrict__ out,
                               uint32_t k0, uint32_t k1) {
    int e = blockIdx.x * blockDim.x + threadIdx.x;
    if (e >= MPAD * FH) return;
    int r = e >> 7, c = e & (FH - 1);
    __nv_bfloat16 h = __float2bfloat16(0.f), l = h;
    if (r < NN) {
        float v = g_dis[r] * (agg[e] + hs[e]) + b[c];
        v = fmaxf(v, 0.0f);
        v = tf_keep(k0, k1, (uint32_t)e) ? 2.0f * v : 0.0f;
        split_bf16(v, h, l);
    }
    size_t base = (size_t)r * (3 * FH);
    out[base + c] = h;
    out[base + FH + c] = l;
    out[base + 2 * FH + c] = h;
}

// ---------------- finish layer2: relu+dropout -> fp32 h2 -------------------
__global__ void k_finish_hid(const float* __restrict__ agg, const float* __restrict__ hs,
                             const float* __restrict__ b, float* __restrict__ out,
                             uint32_t k0, uint32_t k1) {
    int e = blockIdx.x * blockDim.x + threadIdx.x;
    if (e >= NN * FH) return;
    int r = e >> 7, c = e & (FH - 1);
    float v = g_dis[r] * (agg[e] + hs[e]) + b[c];
    v = fmaxf(v, 0.0f);
    out[e] = tf_keep(k0, k1, (uint32_t)e) ? 2.0f * v : 0.0f;
}

// ---------------- finish output GCN layer (F = 40) -------------------------
__global__ void k_finish40(const float* __restrict__ agg, const float* __restrict__ hs,
                           const float* __restrict__ b) {
    int e = blockIdx.x * blockDim.x + threadIdx.x;
    if (e >= NN * FO) return;
    int r = e / FO, c = e - r * FO;
    g_h3[e] = g_dis[r] * (agg[e] + hs[e]) + b[c];
}

// ---------------- dropout -> split bf16 into Abig (comp path) --------------
__global__ void k_dropout_split(const float* __restrict__ in, __nv_bfloat16* __restrict__ out,
                                uint32_t k0, uint32_t k1) {
    int e = blockIdx.x * blockDim.x + threadIdx.x;
    if (e >= MPAD * FC) return;
    int r = e >> 8, c = e & (FC - 1);
    __nv_bfloat16 h = __float2bfloat16(0.f), l = h;
    if (r < NN) {
        float v = tf_keep(k0, k1, (uint32_t)e) ? 2.0f * in[e] : 0.0f;
        split_bf16(v, h, l);
    }
    size_t base = (size_t)r * (3 * FC);
    out[base + c] = h;
    out[base + FC + c] = l;
    out[base + 2 * FC + c] = h;
}

// ---------------- dropout (fp32 in place) -----------------------------------
__global__ void k_dropout(float* __restrict__ buf, int S, uint32_t k0, uint32_t k1) {
    int e = blockIdx.x * blockDim.x + threadIdx.x;
    if (e >= S) return;
    float a = buf[e];
    buf[e] = tf_keep(k0, k1, (uint32_t)e) ? 2.0f * a : 0.0f;
}

// ---------------- SpMM -------------------------------------------------------
__global__ void k_spmm(const int* __restrict__ rows, const int* __restrict__ cols,
                       const float* __restrict__ vals, int P) {
    long long t = (long long)blockIdx.x * blockDim.x + threadIdx.x;
    long long total = (long long)P * 10;
    if (t >= total) return;
    int e = (int)(t / 10);
    int q = (int)(t - (long long)e * 10);
    int r = __ldg(&rows[e]), c = __ldg(&cols[e]);
    float val = __ldg(&vals[e]);
    float4 v = __ldg(reinterpret_cast<const float4*>(g_h3) + (size_t)c * 10 + q);
    v.x *= val; v.y *= val; v.z *= val; v.w *= val;
    red_add_v4(g_hp + ((size_t)r * 10 + q) * 4, v);
}

// ---------------- final: z = hp*(1+c3); log_softmax -------------------------
__global__ void k_final(float* __restrict__ out) {
    int gt = blockIdx.x * blockDim.x + threadIdx.x;
    int w = gt >> 5;
    int lane = gt & 31;
    if (w >= NN) return;

    const float NEG_INF = __int_as_float(0xff800000);
    int c0 = lane, c1 = lane + 32;
    size_t base = (size_t)w * FO;

    float z0 = g_hp[base + c0] * (1.0f + g_c3[base + c0]);
    float z1 = (c1 < FO) ? g_hp[base + c1] * (1.0f + g_c3[base + c1]) : NEG_INF;

    float m = fmaxf(z0, z1);
#pragma unroll
    for (int off = 16; off > 0; off >>= 1)
        m = fmaxf(m, __shfl_xor_sync(0xffffffffu, m, off));

    float s = expf(z0 - m) + ((c1 < FO) ? expf(z1 - m) : 0.0f);
#pragma unroll
    for (int off = 16; off > 0; off >>= 1)
        s += __shfl_xor_sync(0xffffffffu, s, off);

    float lse = logf(s) + m;
    out[base + c0] = z0 - lse;
    if (c1 < FO) out[base + c1] = z1 - lse;
}

// ---------------- host launcher ---------------------------------------------
static inline int cdiv(long long a, int b) { return (int)((a + b - 1) / b); }

extern "C" void kernel_launch(void* const* d_in, const int* in_sizes, int n_in,
                              void* d_out, int out_size) {
    const float* x     = (const float*)d_in[0];
    const float* omega = (const float*)d_in[1];
    const int*   ei    = (const int*)d_in[2];
    const int*   prow  = (const int*)d_in[3];
    const int*   pcol  = (const int*)d_in[4];
    const float* pval  = (const float*)d_in[5];
    const float* Wg1 = (const float*)d_in[6];  const float* bg1 = (const float*)d_in[7];
    const float* Wg2 = (const float*)d_in[8];  const float* bg2 = (const float*)d_in[9];
    const float* Wg3 = (const float*)d_in[10]; const float* bg3 = (const float*)d_in[11];
    const float* Wc1 = (const float*)d_in[12]; const float* bc1 = (const float*)d_in[13];
    const float* Wc2 = (const float*)d_in[14]; const float* bc2 = (const float*)d_in[15];
    const float* Wc3 = (const float*)d_in[16]; const float* bc3 = (const float*)d_in[17];

    int E = in_sizes[2] / 2;
    int P = in_sizes[3];
    const int* src = ei;
    const int* dst = ei + E;

    uint32_t dk[4][2];
    for (int j = 0; j < 4; j++) {
        uint32_t a = 0u, b = (uint32_t)j;
        threefry2x32(0u, 7u, a, b);
        dk[j][0] = a; dk[j][1] = b;
    }

    void *p_deg, *p_hs1, *p_agg1, *p_hs2, *p_agg2, *p_h2;
    void *p_hs3, *p_agg3, *p_hp, *p_c1, *p_c2, *p_c3, *p_abig, *p_wbig;
    cudaGetSymbolAddress(&p_deg, g_deg);
    cudaGetSymbolAddress(&p_hs1, g_hs1);   cudaGetSymbolAddress(&p_agg1, g_agg1);
    cudaGetSymbolAddress(&p_hs2, g_hs2);   cudaGetSymbolAddress(&p_agg2, g_agg2);
    cudaGetSymbolAddress(&p_h2, g_h2);
    cudaGetSymbolAddress(&p_hs3, g_hs3);   cudaGetSymbolAddress(&p_agg3, g_agg3);
    cudaGetSymbolAddress(&p_hp, g_hp);
    cudaGetSymbolAddress(&p_c1, g_c1);     cudaGetSymbolAddress(&p_c2, g_c2);
    cudaGetSymbolAddress(&p_c3, g_c3);
    cudaGetSymbolAddress(&p_abig, g_abig); cudaGetSymbolAddress(&p_wbig, g_wbig);

    __nv_bfloat16* abig = (__nv_bfloat16*)p_abig;
    __nv_bfloat16* wbig = (__nv_bfloat16*)p_wbig;

    cudaStream_t st = 0;
    cudaMemsetAsync(p_deg,  0, NN * sizeof(float), st);
    cudaMemsetAsync(p_agg1, 0, (size_t)NN * FH * sizeof(float), st);
    cudaMemsetAsync(p_agg2, 0, (size_t)NN * FH * sizeof(float), st);
    cudaMemsetAsync(p_agg3, 0, (size_t)NN * FO * sizeof(float), st);
    cudaMemsetAsync(p_hp,   0, (size_t)NN * FO * sizeof(float), st);

    k_deg<<<cdiv(E, 256), 256, 0, st>>>(dst, E);
    k_dis<<<cdiv(NN, 256), 256, 0, st>>>();

    dim3 blk(256);

    // ---- GCN layer 1: Abig=[xh|xl|xh], Wbig=[Wh|Wh|Wl]^T -> hs1=dis*(x@Wg1)
    k_splitA<<<cdiv((long long)MPAD * (FIN / 2), 256), blk, 0, st>>>(x, abig, NN, FIN);
    k_splitW<<<cdiv(FIN * FH, 256), blk, 0, st>>>(Wg1, wbig, FIN, FH);
    mma_gemm<false, false, true><<<dim3(MT, 1), blk, 0, st>>>(
        abig, wbig, nullptr, (float*)p_hs1, NN, 3 * FIN, FH);
    k_agg128<<<cdiv((long long)E * 32, 256), blk, 0, st>>>(
        (const float*)p_hs1, src, dst, E, (float*)p_agg1);
    k_finish_split<<<cdiv(MPAD * FH, 256), blk, 0, st>>>(
        (const float*)p_agg1, (const float*)p_hs1, bg1, abig, dk[0][0], dk[0][1]);

    // ---- GCN layer 2 (Kp = 384) ----
    k_splitW<<<cdiv(FH * FH, 256), blk, 0, st>>>(Wg2, wbig, FH, FH);
    mma_gemm<false, false, true><<<dim3(MT, 1), blk, 0, st>>>(
        abig, wbig, nullptr, (float*)p_hs2, NN, 3 * FH, FH);
    k_agg128<<<cdiv((long long)E * 32, 256), blk, 0, st>>>(
        (const float*)p_hs2, src, dst, E, (float*)p_agg2);
    k_finish_hid<<<cdiv(NN * FH, 256), blk, 0, st>>>(
        (const float*)p_agg2, (const float*)p_hs2, bg2, (float*)p_h2, dk[1][0], dk[1][1]);

    // ---- GCN layer 3 (N = 40, fp32) ----
    sgemm64<false, false, true><<<dim3(cdiv(NN, 64), 1), blk, 0, st>>>(
        (const float*)p_h2, Wg3, nullptr, (float*)p_hs3, NN, FH, FO);
    k_agg40<<<cdiv((long long)E * 10, 256), blk, 0, st>>>(
        (const float*)p_hs3, src, dst, E, (float*)p_agg3);
    k_finish40<<<cdiv(NN * FO, 256), blk, 0, st>>>(
        (const float*)p_agg3, (const float*)p_hs3, bg3);

    // ---- SpMM with partition matrix ----
    k_spmm<<<cdiv((long long)P * 10, 256), blk, 0, st>>>(prow, pcol, pval, P);

    // ---- compensation MLP ----
    k_splitA<<<cdiv((long long)MPAD * (FIN / 2), 256), blk, 0, st>>>(omega, abig, NN, FIN);
    k_splitW<<<cdiv(FIN * FC, 256), blk, 0, st>>>(Wc1, wbig, FIN, FC);
    mma_gemm<true, true, false><<<dim3(MT, 2), blk, 0, st>>>(
        abig, wbig, bc1, (float*)p_c1, NN, 3 * FIN, FC);
    k_dropout_split<<<cdiv(MPAD * FC, 256), blk, 0, st>>>(
        (const float*)p_c1, abig, dk[2][0], dk[2][1]);

    k_splitW<<<cdiv(FC * FC, 256), blk, 0, st>>>(Wc2, wbig, FC, FC);
    mma_gemm<true, true, false><<<dim3(MT, 2), blk, 0, st>>>(
        abig, wbig, bc2, (float*)p_c2, NN, 3 * FC, FC);
    k_dropout<<<cdiv(NN * FC, 256), blk, 0, st>>>((float*)p_c2, NN * FC, dk[3][0], dk[3][1]);

    sgemm64<true, false, false><<<dim3(cdiv(NN, 64), 1), blk, 0, st>>>(
        (const float*)p_c2, Wc3, bc3, (float*)p_c3, NN, FC, FO);

    // ---- combine + log_softmax ----
    k_final<<<cdiv((long long)NN * 32, 256), blk, 0, st>>>((float*)d_out);
}

// round 7
// speedup vs baseline: 1.9995x; 1.2045x over previous
#include <cuda_runtime.h>
#include <cuda_bf16.h>
#include <stdint.h>

#define NN   50000
#define FIN  512
#define FH   128
#define FO   40
#define FC   256
#define MPAD 50048            // 391 * 128
#define MT   391

// ---------------- scratch (device globals; no allocation allowed) ----------
__device__ float g_deg[NN];
__device__ float g_dis[NN];
__device__ float g_hs1[NN * FH];
__device__ float g_agg1[NN * FH];
__device__ float g_hs2[NN * FH];
__device__ float g_agg2[NN * FH];
__device__ float g_h2[NN * FH];
__device__ float g_hs3[NN * FO];
__device__ float g_agg3[NN * FO];
__device__ float g_h3[NN * FO];
__device__ float g_hp[NN * FO];
__device__ float g_c1[NN * FC];
__device__ float g_c2[NN * FC];
__device__ float g_c3[NN * FO];
__device__ __nv_bfloat16 g_abig[(size_t)MPAD * 2 * FIN];    // GCN path A (2-term)
__device__ __nv_bfloat16 g_abig2[(size_t)MPAD * 2 * FIN];   // comp path A (2-term)
__device__ __nv_bfloat16 g_w1[FH * FIN];
__device__ __nv_bfloat16 g_w2[FH * FH];
__device__ __nv_bfloat16 g_wc1[FC * FIN];
__device__ __nv_bfloat16 g_wc2[FC * FC];

// ---------------- threefry2x32 (JAX-compatible, partitionable) -------------
__host__ __device__ __forceinline__ void threefry2x32(uint32_t k0, uint32_t k1,
                                                      uint32_t& x0, uint32_t& x1) {
    uint32_t ks0 = k0, ks1 = k1, ks2 = k0 ^ k1 ^ 0x1BD11BDAu;
    x0 += ks0; x1 += ks1;
#define TF_RND(r) { x0 += x1; x1 = (x1 << (r)) | (x1 >> (32 - (r))); x1 ^= x0; }
    TF_RND(13) TF_RND(15) TF_RND(26) TF_RND(6)   x0 += ks1; x1 += ks2 + 1u;
    TF_RND(17) TF_RND(29) TF_RND(16) TF_RND(24)  x0 += ks2; x1 += ks0 + 2u;
    TF_RND(13) TF_RND(15) TF_RND(26) TF_RND(6)   x0 += ks0; x1 += ks1 + 3u;
    TF_RND(17) TF_RND(29) TF_RND(16) TF_RND(24)  x0 += ks1; x1 += ks2 + 4u;
    TF_RND(13) TF_RND(15) TF_RND(26) TF_RND(6)   x0 += ks2; x1 += ks0 + 5u;
#undef TF_RND
}

__device__ __forceinline__ bool tf_keep(uint32_t k0, uint32_t k1, uint32_t idx) {
    uint32_t x0 = 0u, x1 = idx;
    threefry2x32(k0, k1, x0, x1);
    return (((x0 ^ x1) >> 31) == 0u);
}

__device__ __forceinline__ void red_add_v4(float* p, float4 v) {
    asm volatile("red.global.add.v4.f32 [%0], {%1, %2, %3, %4};"
                 :: "l"(p), "f"(v.x), "f"(v.y), "f"(v.z), "f"(v.w) : "memory");
}

__device__ __forceinline__ void split_bf16(float a, __nv_bfloat16& h, __nv_bfloat16& l) {
    h = __float2bfloat16(a);
    l = __float2bfloat16(a - __bfloat162float(h));
}

__device__ __forceinline__ uint32_t smem_u32(const void* p) {
    uint32_t a;
    asm("{ .reg .u64 t; cvta.to.shared.u64 t, %1; cvt.u32.u64 %0, t; }" : "=r"(a) : "l"(p));
    return a;
}

__device__ __forceinline__ void ldsm_x4(uint32_t* r, uint32_t addr) {
    asm volatile("ldmatrix.sync.aligned.m8n8.x4.shared.b16 {%0,%1,%2,%3}, [%4];"
                 : "=r"(r[0]), "=r"(r[1]), "=r"(r[2]), "=r"(r[3]) : "r"(addr));
}

__device__ __forceinline__ void mma16816(float* c, const uint32_t* a, const uint32_t* b) {
    asm volatile("mma.sync.aligned.m16n8k16.row.col.f32.bf16.bf16.f32 "
                 "{%0,%1,%2,%3}, {%4,%5,%6,%7}, {%8,%9}, {%0,%1,%2,%3};"
                 : "+f"(c[0]), "+f"(c[1]), "+f"(c[2]), "+f"(c[3])
                 : "r"(a[0]), "r"(a[1]), "r"(a[2]), "r"(a[3]), "r"(b[0]), "r"(b[1]));
}

__device__ __forceinline__ void cp_async16(uint32_t saddr, const void* gaddr) {
    asm volatile("cp.async.cg.shared.global [%0], [%1], 16;" :: "r"(saddr), "l"(gaddr));
}
#define CP_COMMIT() asm volatile("cp.async.commit_group;" ::: "memory")
#define CP_WAIT(n)  asm volatile("cp.async.wait_group %0;" :: "n"(n) : "memory")

// ---------------- degree / normalization -----------------------------------
__global__ void k_deg(const int* __restrict__ dst, int E) {
    int i = blockIdx.x * blockDim.x + threadIdx.x;
    if (i < E) atomicAdd(&g_deg[dst[i]], 1.0f);
}
__global__ void k_dis() {
    int i = blockIdx.x * blockDim.x + threadIdx.x;
    if (i < NN) g_dis[i] = rsqrtf(1.0f + g_deg[i]);
}

// ---------------- merged split pass -----------------------------------------
// splitA(x), splitA(omega), splitW(Wg1), splitW(Wg2), splitW(Wc1), splitW(Wc2)
__device__ __forceinline__ void splitA_item(const float* A, __nv_bfloat16* out,
                                            int K, long long i) {
    int K2 = K >> 1;
    int r = (int)(i / K2), kk = (int)(i - (long long)r * K2) * 2;
    __nv_bfloat162 hi2, lo2;
    if (r < NN) {
        float2 a = *reinterpret_cast<const float2*>(A + (size_t)r * K + kk);
        __nv_bfloat16 h0, h1, l0, l1;
        split_bf16(a.x, h0, l0);
        split_bf16(a.y, h1, l1);
        hi2 = __halves2bfloat162(h0, h1);
        lo2 = __halves2bfloat162(l0, l1);
    } else {
        __nv_bfloat16 z = __float2bfloat16(0.f);
        hi2 = __halves2bfloat162(z, z); lo2 = hi2;
    }
    size_t base = (size_t)r * (2 * K);
    *reinterpret_cast<__nv_bfloat162*>(out + base + kk)     = hi2;
    *reinterpret_cast<__nv_bfloat162*>(out + base + K + kk) = lo2;
}

__device__ __forceinline__ void splitW_item(const float* W, __nv_bfloat16* out,
                                            int K, int N, int i) {
    int k = i / N, n = i - k * N;
    out[(size_t)n * K + k] = __float2bfloat16(W[(size_t)k * N + n]);
}

__global__ void k_split_all(const float* __restrict__ x, const float* __restrict__ omega,
                            const float* __restrict__ Wg1, const float* __restrict__ Wg2,
                            const float* __restrict__ Wc1, const float* __restrict__ Wc2) {
    const long long R0 = (long long)MPAD * (FIN / 2);      // x
    const long long R1 = R0;                                // omega
    const long long R2 = FIN * FH, R3 = FH * FH;
    const long long R4 = FIN * FC, R5 = FC * FC;
    long long i = (long long)blockIdx.x * blockDim.x + threadIdx.x;
    if (i < R0) { splitA_item(x, g_abig, FIN, i); return; }
    i -= R0;
    if (i < R1) { splitA_item(omega, g_abig2, FIN, i); return; }
    i -= R1;
    if (i < R2) { splitW_item(Wg1, g_w1, FIN, FH, (int)i); return; }
    i -= R2;
    if (i < R3) { splitW_item(Wg2, g_w2, FH, FH, (int)i); return; }
    i -= R3;
    if (i < R4) { splitW_item(Wc1, g_wc1, FIN, FC, (int)i); return; }
    i -= R4;
    if (i < R5) { splitW_item(Wc2, g_wc2, FC, FC, (int)i); return; }
}

// ---------------- bf16 MMA GEMM body (cp.async double-buffered) ------------
// C[M,N] = Abig[Mpad,Kp] @ W[N,KB]^T, where tile t of A (k0=t*64) multiplies
// W columns (k0 % KB). Kp = 2*KB (two split terms vs same W).
struct GemmP {
    const __nv_bfloat16* A; const __nv_bfloat16* B; const float* bias; float* C;
    int M, Kp, KB, N, scale, relu;
};

__device__ __forceinline__ void gemm_body(const GemmP& p, int bn) {
    __shared__ __align__(16) __nv_bfloat16 As[2][128][72];
    __shared__ __align__(16) __nv_bfloat16 Bs[2][128][72];

    int tid = threadIdx.x, wid = tid >> 5, lane = tid & 31;
    int bm = blockIdx.x * 128;
    int wm = (wid & 3) << 5;
    int wn = (wid >> 2) << 6;

    float acc[2][8][4];
#pragma unroll
    for (int i = 0; i < 2; i++)
#pragma unroll
        for (int j = 0; j < 8; j++)
#pragma unroll
            for (int q = 0; q < 4; q++) acc[i][j][q] = 0.0f;

    int mat = lane >> 3, r8 = lane & 7;
    int nT = p.Kp >> 6;

    auto load_tile = [&](int t, int buf) {
        int k0 = t << 6;
        int bk0 = (k0 >= p.KB) ? k0 - p.KB : k0;
#pragma unroll
        for (int i = 0; i < 4; i++) {
            int idx = tid + i * 256;
            int r = idx >> 3, c = idx & 7;
            cp_async16(smem_u32(&As[buf][r][c * 8]),
                       p.A + (size_t)(bm + r) * p.Kp + k0 + c * 8);
            cp_async16(smem_u32(&Bs[buf][r][c * 8]),
                       p.B + (size_t)(bn + r) * p.KB + bk0 + c * 8);
        }
        CP_COMMIT();
    };

    load_tile(0, 0);

    for (int t = 0; t < nT; t++) {
        int cur = t & 1;
        if (t + 1 < nT) {
            load_tile(t + 1, cur ^ 1);
            CP_WAIT(1);
        } else {
            CP_WAIT(0);
        }
        __syncthreads();

#pragma unroll
        for (int kk = 0; kk < 64; kk += 16) {
            uint32_t a[2][4];
#pragma unroll
            for (int mf = 0; mf < 2; mf++) {
                uint32_t addr = smem_u32(
                    &As[cur][wm + mf * 16 + ((mat & 1) << 3) + r8][kk + ((mat >> 1) << 3)]);
                ldsm_x4(a[mf], addr);
            }
            uint32_t b[8][2];
#pragma unroll
            for (int nf2 = 0; nf2 < 4; nf2++) {
                uint32_t addr = smem_u32(
                    &Bs[cur][wn + nf2 * 16 + ((mat >> 1) << 3) + r8][kk + ((mat & 1) << 3)]);
                uint32_t tr[4];
                ldsm_x4(tr, addr);
                b[nf2 * 2][0] = tr[0]; b[nf2 * 2][1] = tr[1];
                b[nf2 * 2 + 1][0] = tr[2]; b[nf2 * 2 + 1][1] = tr[3];
            }
#pragma unroll
            for (int mf = 0; mf < 2; mf++)
#pragma unroll
                for (int nf = 0; nf < 8; nf++)
                    mma16816(acc[mf][nf], a[mf], b[nf]);
        }
        __syncthreads();
    }

    int g = lane >> 2, tg = lane & 3;
#pragma unroll
    for (int mf = 0; mf < 2; mf++) {
#pragma unroll
        for (int half = 0; half < 2; half++) {
            int r = bm + wm + mf * 16 + g + half * 8;
            if (r >= p.M) continue;
            float sc = p.scale ? g_dis[r] : 1.0f;
#pragma unroll
            for (int nf = 0; nf < 8; nf++) {
                int c = bn + wn + nf * 8 + tg * 2;
                float v0 = acc[mf][nf][half * 2 + 0];
                float v1 = acc[mf][nf][half * 2 + 1];
                if (p.bias) { v0 += p.bias[c]; v1 += p.bias[c + 1]; }
                if (p.relu) { v0 = fmaxf(v0, 0.0f); v1 = fmaxf(v1, 0.0f); }
                if (p.scale) { v0 *= sc; v1 *= sc; }
                *reinterpret_cast<float2*>(&p.C[(size_t)r * p.N + c]) = make_float2(v0, v1);
            }
        }
    }
}

// fat GEMM: blockIdx.y < yA -> pa (bn = y*128) else pb (bn = (y-yA)*128)
__global__ void __launch_bounds__(256)
k_gemm_fat(GemmP pa, GemmP pb, int yA) {
    if ((int)blockIdx.y < yA) gemm_body(pa, blockIdx.y * 128);
    else                      gemm_body(pb, (blockIdx.y - yA) * 128);
}

// ---------------- SGEMM 64x64x16 fp32 fat (two N=40 layers) ----------------
struct SgP {
    const float* A; const float* W; const float* bias; float* C;
    int K, scale;
};

__device__ __forceinline__ void sgemm_body(const SgP& p) {
    const int BM = 64, BN = 64, BK = 16, N = FO;
    __shared__ float As[BK][BM + 4];
    __shared__ float Ws[BK][BN];

    int tid = threadIdx.x;
    int bm = blockIdx.x * BM;
    int tx = tid & 15, ty = tid >> 4;
    int arow = tid >> 2, acol4 = tid & 3;
    int wrow = tid >> 4, wcol4 = tid & 15;

    float acc[4][4];
#pragma unroll
    for (int i = 0; i < 4; i++)
#pragma unroll
        for (int j = 0; j < 4; j++) acc[i][j] = 0.0f;

    for (int k0 = 0; k0 < p.K; k0 += BK) {
        float4 av = make_float4(0.f, 0.f, 0.f, 0.f);
        int gr = bm + arow;
        if (gr < NN)
            av = *reinterpret_cast<const float4*>(&p.A[(size_t)gr * p.K + k0 + acol4 * 4]);
        As[acol4 * 4 + 0][arow] = av.x;
        As[acol4 * 4 + 1][arow] = av.y;
        As[acol4 * 4 + 2][arow] = av.z;
        As[acol4 * 4 + 3][arow] = av.w;

        float4 wv = make_float4(0.f, 0.f, 0.f, 0.f);
        int gc = wcol4 * 4;
        if (gc < N)
            wv = *reinterpret_cast<const float4*>(&p.W[(size_t)(k0 + wrow) * N + gc]);
        Ws[wrow][wcol4 * 4 + 0] = wv.x;
        Ws[wrow][wcol4 * 4 + 1] = wv.y;
        Ws[wrow][wcol4 * 4 + 2] = wv.z;
        Ws[wrow][wcol4 * 4 + 3] = wv.w;

        __syncthreads();
#pragma unroll
        for (int k = 0; k < BK; k++) {
            float a[4], w[4];
#pragma unroll
            for (int i = 0; i < 4; i++) a[i] = As[k][ty * 4 + i];
#pragma unroll
            for (int j = 0; j < 4; j++) w[j] = Ws[k][tx * 4 + j];
#pragma unroll
            for (int i = 0; i < 4; i++)
#pragma unroll
                for (int j = 0; j < 4; j++) acc[i][j] = fmaf(a[i], w[j], acc[i][j]);
        }
        __syncthreads();
    }

#pragma unroll
    for (int i = 0; i < 4; i++) {
        int r = bm + ty * 4 + i;
        if (r >= NN) continue;
        float sc = p.scale ? g_dis[r] : 1.0f;
#pragma unroll
        for (int j = 0; j < 4; j++) {
            int c = tx * 4 + j;
            if (c >= N) continue;
            float v = acc[i][j];
            if (p.bias) v += p.bias[c];
            if (p.scale) v *= sc;
            p.C[(size_t)r * N + c] = v;
        }
    }
}

__global__ void k_sgemm_fat(SgP pa, SgP pb) {
    if (blockIdx.y == 0) sgemm_body(pa);
    else                 sgemm_body(pb);
}

// ---------------- fat: agg128 + dropout_split (comp c1 -> abig2) -----------
__global__ void k_agg_dropsplit(const float* __restrict__ hs, const int* __restrict__ src,
                                const int* __restrict__ dst, int E, float* __restrict__ agg,
                                int aggBlocks, const float* __restrict__ cin,
                                __nv_bfloat16* __restrict__ aout,
                                uint32_t k0, uint32_t k1) {
    if ((int)blockIdx.x < aggBlocks) {
        long long t = (long long)blockIdx.x * blockDim.x + threadIdx.x;
        if (t >= (long long)E * 32) return;
        int e = (int)(t >> 5);
        int q = (int)(t & 31);
        int s = __ldg(&src[e]), d = __ldg(&dst[e]);
        float4 v = __ldg(reinterpret_cast<const float4*>(hs) + (size_t)s * 32 + q);
        red_add_v4(agg + ((size_t)d * 32 + q) * 4, v);
    } else {
        int e = (blockIdx.x - aggBlocks) * blockDim.x + threadIdx.x;
        if (e >= MPAD * FC) return;
        int r = e >> 8, c = e & (FC - 1);
        __nv_bfloat16 h = __float2bfloat16(0.f), l = h;
        if (r < NN) {
            float v = tf_keep(k0, k1, (uint32_t)e) ? 2.0f * cin[e] : 0.0f;
            split_bf16(v, h, l);
        }
        size_t base = (size_t)r * (2 * FC);
        aout[base + c] = h;
        aout[base + FC + c] = l;
    }
}

// ---------------- fat: agg128 + dropout (comp c2 in place) -----------------
__global__ void k_agg_drop(const float* __restrict__ hs, const int* __restrict__ src,
                           const int* __restrict__ dst, int E, float* __restrict__ agg,
                           int aggBlocks, float* __restrict__ buf,
                           uint32_t k0, uint32_t k1) {
    if ((int)blockIdx.x < aggBlocks) {
        long long t = (long long)blockIdx.x * blockDim.x + threadIdx.x;
        if (t >= (long long)E * 32) return;
        int e = (int)(t >> 5);
        int q = (int)(t & 31);
        int s = __ldg(&src[e]), d = __ldg(&dst[e]);
        float4 v = __ldg(reinterpret_cast<const float4*>(hs) + (size_t)s * 32 + q);
        red_add_v4(agg + ((size_t)d * 32 + q) * 4, v);
    } else {
        int e = (blockIdx.x - aggBlocks) * blockDim.x + threadIdx.x;
        if (e >= NN * FC) return;
        float a = buf[e];
        buf[e] = tf_keep(k0, k1, (uint32_t)e) ? 2.0f * a : 0.0f;
    }
}

// ---------------- agg40 ------------------------------------------------------
__global__ void k_agg40(const float* __restrict__ hs, const int* __restrict__ src,
                        const int* __restrict__ dst, int E, float* __restrict__ agg) {
    long long t = (long long)blockIdx.x * blockDim.x + threadIdx.x;
    if (t >= (long long)E * 10) return;
    int e = (int)(t / 10);
    int q = (int)(t - (long long)e * 10);
    int s = __ldg(&src[e]), d = __ldg(&dst[e]);
    float4 v = __ldg(reinterpret_cast<const float4*>(hs) + (size_t)s * 10 + q);
    red_add_v4(agg + ((size_t)d * 10 + q) * 4, v);
}

// ---------------- finish layer1: relu+dropout -> split bf16 into abig ------
__global__ void k_finish_split(const float* __restrict__ agg, const float* __restrict__ hs,
                               const float* __restrict__ b, __nv_bfloat16* __restrict__ out,
                               uint32_t k0, uint32_t k1) {
    int e = blockIdx.x * blockDim.x + threadIdx.x;
    if (e >= MPAD * FH) return;
    int r = e >> 7, c = e & (FH - 1);
    __nv_bfloat16 h = __float2bfloat16(0.f), l = h;
    if (r < NN) {
        float v = g_dis[r] * (agg[e] + hs[e]) + b[c];
        v = fmaxf(v, 0.0f);
        v = tf_keep(k0, k1, (uint32_t)e) ? 2.0f * v : 0.0f;
        split_bf16(v, h, l);
    }
    size_t base = (size_t)r * (2 * FH);
    out[base + c] = h;
    out[base + FH + c] = l;
}

// ---------------- finish layer2: relu+dropout -> fp32 h2 -------------------
__global__ void k_finish_hid(const float* __restrict__ agg, const float* __restrict__ hs,
                             const float* __restrict__ b, float* __restrict__ out,
                             uint32_t k0, uint32_t k1) {
    int e = blockIdx.x * blockDim.x + threadIdx.x;
    if (e >= NN * FH) return;
    int r = e >> 7, c = e & (FH - 1);
    float v = g_dis[r] * (agg[e] + hs[e]) + b[c];
    v = fmaxf(v, 0.0f);
    out[e] = tf_keep(k0, k1, (uint32_t)e) ? 2.0f * v : 0.0f;
}

// ---------------- finish output GCN layer (F = 40) -------------------------
__global__ void k_finish40(const float* __restrict__ agg, const float* __restrict__ hs,
                           const float* __restrict__ b) {
    int e = blockIdx.x * blockDim.x + threadIdx.x;
    if (e >= NN * FO) return;
    int r = e / FO, c = e - r * FO;
    g_h3[e] = g_dis[r] * (agg[e] + hs[e]) + b[c];
}

// ---------------- SpMM -------------------------------------------------------
__global__ void k_spmm(const int* __restrict__ rows, const int* __restrict__ cols,
                       const float* __restrict__ vals, int P) {
    long long t = (long long)blockIdx.x * blockDim.x + threadIdx.x;
    if (t >= (long long)P * 10) return;
    int e = (int)(t / 10);
    int q = (int)(t - (long long)e * 10);
    int r = __ldg(&rows[e]), c = __ldg(&cols[e]);
    float val = __ldg(&vals[e]);
    float4 v = __ldg(reinterpret_cast<const float4*>(g_h3) + (size_t)c * 10 + q);
    v.x *= val; v.y *= val; v.z *= val; v.w *= val;
    red_add_v4(g_hp + ((size_t)r * 10 + q) * 4, v);
}

// ---------------- final: z = hp*(1+c3); log_softmax -------------------------
__global__ void k_final(float* __restrict__ out) {
    int gt = blockIdx.x * blockDim.x + threadIdx.x;
    int w = gt >> 5;
    int lane = gt & 31;
    if (w >= NN) return;

    const float NEG_INF = __int_as_float(0xff800000);
    int c0 = lane, c1 = lane + 32;
    size_t base = (size_t)w * FO;

    float z0 = g_hp[base + c0] * (1.0f + g_c3[base + c0]);
    float z1 = (c1 < FO) ? g_hp[base + c1] * (1.0f + g_c3[base + c1]) : NEG_INF;

    float m = fmaxf(z0, z1);
#pragma unroll
    for (int off = 16; off > 0; off >>= 1)
        m = fmaxf(m, __shfl_xor_sync(0xffffffffu, m, off));

    float s = expf(z0 - m) + ((c1 < FO) ? expf(z1 - m) : 0.0f);
#pragma unroll
    for (int off = 16; off > 0; off >>= 1)
        s += __shfl_xor_sync(0xffffffffu, s, off);

    float lse = logf(s) + m;
    out[base + c0] = z0 - lse;
    if (c1 < FO) out[base + c1] = z1 - lse;
}

// ---------------- host launcher ---------------------------------------------
static inline int cdiv(long long a, int b) { return (int)((a + b - 1) / b); }

extern "C" void kernel_launch(void* const* d_in, const int* in_sizes, int n_in,
                              void* d_out, int out_size) {
    const float* x     = (const float*)d_in[0];
    const float* omega = (const float*)d_in[1];
    const int*   ei    = (const int*)d_in[2];
    const int*   prow  = (const int*)d_in[3];
    const int*   pcol  = (const int*)d_in[4];
    const float* pval  = (const float*)d_in[5];
    const float* Wg1 = (const float*)d_in[6];  const float* bg1 = (const float*)d_in[7];
    const float* Wg2 = (const float*)d_in[8];  const float* bg2 = (const float*)d_in[9];
    const float* Wg3 = (const float*)d_in[10]; const float* bg3 = (const float*)d_in[11];
    const float* Wc1 = (const float*)d_in[12]; const float* bc1 = (const float*)d_in[13];
    const float* Wc2 = (const float*)d_in[14]; const float* bc2 = (const float*)d_in[15];
    const float* Wc3 = (const float*)d_in[16]; const float* bc3 = (const float*)d_in[17];

    int E = in_sizes[2] / 2;
    int P = in_sizes[3];
    const int* src = ei;
    const int* dst = ei + E;

    uint32_t dk[4][2];
    for (int j = 0; j < 4; j++) {
        uint32_t a = 0u, b = (uint32_t)j;
        threefry2x32(0u, 7u, a, b);
        dk[j][0] = a; dk[j][1] = b;
    }

    void *p_deg, *p_hs1, *p_agg1, *p_hs2, *p_agg2, *p_h2;
    void *p_hs3, *p_agg3, *p_hp, *p_c1, *p_c2, *p_c3;
    void *p_abig, *p_abig2, *p_w1, *p_w2, *p_wc1, *p_wc2;
    cudaGetSymbolAddress(&p_deg, g_deg);
    cudaGetSymbolAddress(&p_hs1, g_hs1);   cudaGetSymbolAddress(&p_agg1, g_agg1);
    cudaGetSymbolAddress(&p_hs2, g_hs2);   cudaGetSymbolAddress(&p_agg2, g_agg2);
    cudaGetSymbolAddress(&p_h2, g_h2);
    cudaGetSymbolAddress(&p_hs3, g_hs3);   cudaGetSymbolAddress(&p_agg3, g_agg3);
    cudaGetSymbolAddress(&p_hp, g_hp);
    cudaGetSymbolAddress(&p_c1, g_c1);     cudaGetSymbolAddress(&p_c2, g_c2);
    cudaGetSymbolAddress(&p_c3, g_c3);
    cudaGetSymbolAddress(&p_abig, g_abig); cudaGetSymbolAddress(&p_abig2, g_abig2);
    cudaGetSymbolAddress(&p_w1, g_w1);     cudaGetSymbolAddress(&p_w2, g_w2);
    cudaGetSymbolAddress(&p_wc1, g_wc1);   cudaGetSymbolAddress(&p_wc2, g_wc2);

    __nv_bfloat16* abig  = (__nv_bfloat16*)p_abig;
    __nv_bfloat16* abig2 = (__nv_bfloat16*)p_abig2;

    cudaStream_t st = 0;
    cudaMemsetAsync(p_deg,  0, NN * sizeof(float), st);
    cudaMemsetAsync(p_agg1, 0, (size_t)NN * FH * sizeof(float), st);
    cudaMemsetAsync(p_agg2, 0, (size_t)NN * FH * sizeof(float), st);
    cudaMemsetAsync(p_agg3, 0, (size_t)NN * FO * sizeof(float), st);
    cudaMemsetAsync(p_hp,   0, (size_t)NN * FO * sizeof(float), st);

    k_deg<<<cdiv(E, 256), 256, 0, st>>>(dst, E);
    k_dis<<<cdiv(NN, 256), 256, 0, st>>>();

    dim3 blk(256);

    // ---- all splits in one pass ----
    const long long SPLIT_TOTAL = 2LL * MPAD * (FIN / 2) + FIN * FH + FH * FH
                                + FIN * FC + FC * FC;
    k_split_all<<<cdiv(SPLIT_TOTAL, 256), blk, 0, st>>>(x, omega, Wg1, Wg2, Wc1, Wc2);

    int aggBlocks = cdiv((long long)E * 32, 256);

    // ---- fat GEMM #1: GCN L1 (N=128) + comp L1 (N=256) ----
    GemmP g1{abig, (const __nv_bfloat16*)p_w1, nullptr, (float*)p_hs1,
             NN, 2 * FIN, FIN, FH, 1, 0};
    GemmP c1{abig2, (const __nv_bfloat16*)p_wc1, bc1, (float*)p_c1,
             NN, 2 * FIN, FIN, FC, 0, 1};
    k_gemm_fat<<<dim3(MT, 3), blk, 0, st>>>(g1, c1, 1);

    // ---- fat: agg1 + dropout_split(c1 -> abig2) ----
    k_agg_dropsplit<<<aggBlocks + cdiv(MPAD * FC, 256), blk, 0, st>>>(
        (const float*)p_hs1, src, dst, E, (float*)p_agg1, aggBlocks,
        (const float*)p_c1, abig2, dk[2][0], dk[2][1]);

    // ---- finish L1 -> abig (2-term) ----
    k_finish_split<<<cdiv(MPAD * FH, 256), blk, 0, st>>>(
        (const float*)p_agg1, (const float*)p_hs1, bg1, abig, dk[0][0], dk[0][1]);

    // ---- fat GEMM #2: GCN L2 (Kp=256) + comp L2 (Kp=512) ----
    GemmP g2{abig, (const __nv_bfloat16*)p_w2, nullptr, (float*)p_hs2,
             NN, 2 * FH, FH, FH, 1, 0};
    GemmP c2{abig2, (const __nv_bfloat16*)p_wc2, bc2, (float*)p_c2,
             NN, 2 * FC, FC, FC, 0, 1};
    k_gemm_fat<<<dim3(MT, 3), blk, 0, st>>>(g2, c2, 1);

    // ---- fat: agg2 + dropout(c2) ----
    k_agg_drop<<<aggBlocks + cdiv(NN * FC, 256), blk, 0, st>>>(
        (const float*)p_hs2, src, dst, E, (float*)p_agg2, aggBlocks,
        (float*)p_c2, dk[3][0], dk[3][1]);

    // ---- finish L2 -> h2 (fp32) ----
    k_finish_hid<<<cdiv(NN * FH, 256), blk, 0, st>>>(
        (const float*)p_agg2, (const float*)p_hs2, bg2, (float*)p_h2, dk[1][0], dk[1][1]);

    // ---- fat sgemm: GCN L3 (h2 @ Wg3, scale) + comp L3 (c2 @ Wc3 + bc3) ----
    SgP s3{(const float*)p_h2, Wg3, nullptr, (float*)p_hs3, FH, 1};
    SgP sc3{(const float*)p_c2, Wc3, bc3, (float*)p_c3, FC, 0};
    k_sgemm_fat<<<dim3(cdiv(NN, 64), 2), blk, 0, st>>>(s3, sc3);

    // ---- L3 aggregate + finish ----
    k_agg40<<<cdiv((long long)E * 10, 256), blk, 0, st>>>(
        (const float*)p_hs3, src, dst, E, (float*)p_agg3);
    k_finish40<<<cdiv(NN * FO, 256), blk, 0, st>>>(
        (const float*)p_agg3, (const float*)p_hs3, bg3);

    // ---- SpMM with partition matrix ----
    k_spmm<<<cdiv((long long)P * 10, 256), blk, 0, st>>>(prow, pcol, pval, P);

    // ---- combine + log_softmax ----
    k_final<<<cdiv((long long)NN * 32, 256), blk, 0, st>>>((float*)d_out);
}